// round 10
// baseline (speedup 1.0000x reference)
#include <cuda_runtime.h>
#include <cuda_bf16.h>
#include <math.h>
#include <stdint.h>

// Problem constants
#define BB   256      // batch
#define TT   256      // time steps
#define ID   256      // input dim
#define HH   1024     // hidden dim
#define GG   4096     // 4*H gates

// Step-kernel tiling (int8 path): chunk = 128 k-bytes per row
#define KCB         128                // k bytes per chunk (s8)
#define NCH         (HH / KCB)         // 8 chunks
#define A_STAGE     16384              // 64 rows x 128B x 2 mats
#define B_BASE      32768
#define B_STAGE     32768              // 128 rows x 128B x 2 mats
#define PRE_BASE    98304
#define PRE_ROW     544                // 512 data + 32 pad
#define DYN_SMEM    (PRE_BASE + 64 * PRE_ROW)   // 133,120
// Pre-GEMM smem: single stage, Ahi/Alo 16K + Bhi/Blo 16K
#define PRE_SMEM    65536

typedef unsigned long long ull;

// Scratch (device globals: allocation-free rule)
__device__ float g_pre[(size_t)BB * TT * GG];        // 1 GiB input-gate precompute
__device__ __align__(128) signed char g_uq_hi[(size_t)GG * HH];  // U^T int8 hi
__device__ __align__(128) signed char g_uq_lo[(size_t)GG * HH];  // U^T int8 lo
__device__ float g_uscale[GG];                        // per-g-row scale (max/127)
__device__ __nv_bfloat16 g_wt_hi[GG * ID];           // folded W^T bf16 split hi
__device__ __nv_bfloat16 g_wt_lo[GG * ID];           // folded W^T bf16 split lo
__device__ __nv_bfloat16 g_x_hi[(size_t)BB * TT * ID];   // X bf16 split hi
__device__ __nv_bfloat16 g_x_lo[(size_t)BB * TT * ID];   // X bf16 split lo
__device__ __align__(128) signed char g_hq_hi[2][BB * HH];   // h ping-pong int8 hi
__device__ __align__(128) signed char g_hq_lo[2][BB * HH];   // h ping-pong int8 lo
__device__ __align__(128) unsigned g_bar4[4][32];    // per-mt barriers (padded)

// ---------------------------------------------------------------------------
// helpers
// ---------------------------------------------------------------------------
__device__ __forceinline__ float fast_sigmoid(float x) {
    float e = __expf(-x);
    return __fdividef(1.0f, 1.0f + e);
}
__device__ __forceinline__ float fast_tanh(float x) {
    float e = __expf(2.0f * x);
    return 1.0f - __fdividef(2.0f, e + 1.0f);
}
__device__ __forceinline__ void cp_async16(uint32_t dst, const void* src) {
    asm volatile("cp.async.cg.shared.global [%0], [%1], 16;" :: "r"(dst), "l"(src));
}
__device__ __forceinline__ void ldsm_x4(uint32_t* r, uint32_t addr) {
    asm volatile("ldmatrix.sync.aligned.m8n8.x4.shared.b16 {%0,%1,%2,%3}, [%4];"
                 : "=r"(r[0]), "=r"(r[1]), "=r"(r[2]), "=r"(r[3]) : "r"(addr));
}
// bf16 x bf16 -> f32 accum (pre-GEMM)
__device__ __forceinline__ void mma_bf16(float* d, const uint32_t* a, const uint32_t* b) {
    asm volatile("mma.sync.aligned.m16n8k16.row.col.f32.bf16.bf16.f32 "
                 "{%0,%1,%2,%3}, {%4,%5,%6,%7}, {%8,%9}, {%0,%1,%2,%3};"
                 : "+f"(d[0]), "+f"(d[1]), "+f"(d[2]), "+f"(d[3])
                 : "r"(a[0]), "r"(a[1]), "r"(a[2]), "r"(a[3]), "r"(b[0]), "r"(b[1]));
}
// s8 x s8 -> s32 accum, k32
__device__ __forceinline__ void mma_s8(int* d, const uint32_t* a, uint32_t b0, uint32_t b1) {
    asm volatile("mma.sync.aligned.m16n8k32.row.col.s32.s8.s8.s32 "
                 "{%0,%1,%2,%3}, {%4,%5,%6,%7}, {%8,%9}, {%0,%1,%2,%3};"
                 : "+r"(d[0]), "+r"(d[1]), "+r"(d[2]), "+r"(d[3])
                 : "r"(a[0]), "r"(a[1]), "r"(a[2]), "r"(a[3]), "r"(b0), "r"(b1));
}

// ---------------------------------------------------------------------------
// Kernel A: fold Wy into W row 255, transpose, bf16-split -> g_wt_hi/lo[g][k]
// ---------------------------------------------------------------------------
__global__ void wt_split_kernel(const float* __restrict__ W,
                                const float* __restrict__ Wy) {
    __shared__ float tile[32][33];
    const int kb = blockIdx.x * 32;
    const int gb = blockIdx.y * 32;
    const int tx = threadIdx.x & 31;
    const int ty = threadIdx.x >> 5;
#pragma unroll
    for (int i = 0; i < 32; i += 8) {
        int krow = kb + ty + i;
        float v = W[(size_t)krow * GG + gb + tx];
        if (krow == ID - 1) v += Wy[gb + tx];
        tile[ty + i][tx] = v;
    }
    __syncthreads();
#pragma unroll
    for (int i = 0; i < 32; i += 8) {
        int g = gb + ty + i;
        int k = kb + tx;
        float v = tile[tx][ty + i];
        __nv_bfloat16 hi = __float2bfloat16(v);
        __nv_bfloat16 lo = __float2bfloat16(v - __bfloat162float(hi));
        g_wt_hi[g * ID + k] = hi;
        g_wt_lo[g * ID + k] = lo;
    }
}

// ---------------------------------------------------------------------------
// Kernel B1: per-g-row scale of U^T: g_uscale[g] = max_k |U[k][g]| / 127
// ---------------------------------------------------------------------------
__global__ void u_scale_kernel(const float* __restrict__ U) {
    __shared__ float red[8][32];
    const int gl = threadIdx.x & 31;
    const int kseg = threadIdx.x >> 5;        // 0..7
    const int g = blockIdx.x * 32 + gl;
    float m = 0.f;
    for (int kk = 0; kk < 128; ++kk)
        m = fmaxf(m, fabsf(U[(size_t)(kseg * 128 + kk) * GG + g]));
    red[kseg][gl] = m;
    __syncthreads();
    if (kseg == 0) {
        float mm = red[0][gl];
#pragma unroll
        for (int i = 1; i < 8; ++i) mm = fmaxf(mm, red[i][gl]);
        g_uscale[g] = fmaxf(mm, 1e-20f) * (1.0f / 127.0f);
    }
}

// ---------------------------------------------------------------------------
// Kernel B2: U^T two-level int8 quantize: U[k][g] = s[g]*(Qhi + Qlo/254)
// ---------------------------------------------------------------------------
__global__ void u_quant_kernel(const float* __restrict__ U) {
    __shared__ float tile[32][33];
    const int kb = blockIdx.x * 32;
    const int gb = blockIdx.y * 32;
    const int tx = threadIdx.x & 31;
    const int ty = threadIdx.x >> 5;
#pragma unroll
    for (int i = 0; i < 32; i += 8)
        tile[ty + i][tx] = U[(size_t)(kb + ty + i) * GG + gb + tx];
    __syncthreads();
#pragma unroll
    for (int i = 0; i < 32; i += 8) {
        int g = gb + ty + i;
        int k = kb + tx;
        float s = g_uscale[g];
        float f = __fdividef(tile[tx][ty + i], s);
        int qh = __float2int_rn(f);
        int ql = __float2int_rn((f - (float)qh) * 254.0f);
        g_uq_hi[(size_t)g * HH + k] = (signed char)qh;
        g_uq_lo[(size_t)g * HH + k] = (signed char)ql;
    }
}

// ---------------------------------------------------------------------------
// Kernel C: X bf16 split
// ---------------------------------------------------------------------------
__global__ void x_split_kernel(const float* __restrict__ X) {
    size_t i4 = (size_t)blockIdx.x * blockDim.x + threadIdx.x;
    float4 v = *(const float4*)(X + i4 * 4);
    float f[4] = {v.x, v.y, v.z, v.w};
    __nv_bfloat16 hi[4], lo[4];
#pragma unroll
    for (int e = 0; e < 4; ++e) {
        hi[e] = __float2bfloat16(f[e]);
        lo[e] = __float2bfloat16(f[e] - __bfloat162float(hi[e]));
    }
    *(__nv_bfloat162*)(g_x_hi + i4 * 4)     = __nv_bfloat162(hi[0], hi[1]);
    *(__nv_bfloat162*)(g_x_hi + i4 * 4 + 2) = __nv_bfloat162(hi[2], hi[3]);
    *(__nv_bfloat162*)(g_x_lo + i4 * 4)     = __nv_bfloat162(lo[0], lo[1]);
    *(__nv_bfloat162*)(g_x_lo + i4 * 4 + 2) = __nv_bfloat162(lo[2], lo[3]);
}

// ---------------------------------------------------------------------------
// Kernel D: tensorized pre-GEMM (occ-2, single stage, bf16 3-pass). Unchanged.
// ---------------------------------------------------------------------------
__global__ __launch_bounds__(256, 2) void pre_gemm_mma(
    const float* __restrict__ bias) {
    extern __shared__ char dsm[];
    const uint32_t sA = (uint32_t)__cvta_generic_to_shared(dsm);
    const uint32_t sB = sA + 32768;

    const int tid = threadIdx.x;
    const int wid = tid >> 5;
    const int lane = tid & 31;
    const int mwarp = wid >> 1;
    const int nwarp = wid & 1;
    const int m0 = blockIdx.y * 128;
    const int n0 = blockIdx.x * 128;

    float acc[2][8][4];
#pragma unroll
    for (int mb = 0; mb < 2; ++mb)
#pragma unroll
        for (int nb = 0; nb < 8; ++nb)
#pragma unroll
            for (int r = 0; r < 4; ++r) acc[mb][nb][r] = 0.f;

    for (int kb = 0; kb < ID / 64; ++kb) {
        const int k0 = kb * 64;
        __syncthreads();
#pragma unroll
        for (int i = 0; i < 8; ++i) {
            int idx = i * 256 + tid;
            int mat = idx >> 10;
            int row = (idx >> 3) & 127;
            int gk = idx & 7;
            const __nv_bfloat16* src = (mat ? g_x_lo : g_x_hi) +
                (size_t)(m0 + row) * ID + k0 + gk * 8;
            uint32_t dst = sA + mat * 16384 + row * 128 + ((gk ^ (row & 7)) << 4);
            cp_async16(dst, src);
        }
#pragma unroll
        for (int i = 0; i < 8; ++i) {
            int idx = i * 256 + tid;
            int mat = idx >> 10;
            int row = (idx >> 3) & 127;
            int gk = idx & 7;
            const __nv_bfloat16* src = (mat ? g_wt_lo : g_wt_hi) +
                (size_t)(n0 + row) * ID + k0 + gk * 8;
            uint32_t dst = sB + mat * 16384 + row * 128 + ((gk ^ (row & 7)) << 4);
            cp_async16(dst, src);
        }
        asm volatile("cp.async.commit_group;" ::: "memory");
        asm volatile("cp.async.wait_group 0;" ::: "memory");
        __syncthreads();

#pragma unroll
        for (int ks = 0; ks < 4; ++ks) {
            uint32_t a_hi[2][4], a_lo[2][4];
#pragma unroll
            for (int mb = 0; mb < 2; ++mb) {
                uint32_t arow = mwarp * 32 + mb * 16 + (lane & 15);
                int gk = ks * 2 + (lane >> 4);
                uint32_t off = arow * 128 + ((gk ^ (arow & 7)) << 4);
                ldsm_x4(a_hi[mb], sA + off);
                ldsm_x4(a_lo[mb], sA + 16384 + off);
            }
#pragma unroll
            for (int nbp = 0; nbp < 4; ++nbp) {
                uint32_t brow = nwarp * 64 + nbp * 16 + (lane & 7) + (lane >> 4) * 8;
                int gk = ks * 2 + ((lane >> 3) & 1);
                uint32_t off = brow * 128 + ((gk ^ (brow & 7)) << 4);
                uint32_t b_hi4[4], b_lo4[4];
                ldsm_x4(b_hi4, sB + off);
                ldsm_x4(b_lo4, sB + 16384 + off);
#pragma unroll
                for (int h = 0; h < 2; ++h) {
#pragma unroll
                    for (int mb = 0; mb < 2; ++mb) {
                        mma_bf16(acc[mb][nbp * 2 + h], a_hi[mb], b_hi4 + h * 2);
                        mma_bf16(acc[mb][nbp * 2 + h], a_hi[mb], b_lo4 + h * 2);
                        mma_bf16(acc[mb][nbp * 2 + h], a_lo[mb], b_hi4 + h * 2);
                    }
                }
            }
        }
    }

#pragma unroll
    for (int nb = 0; nb < 8; ++nb) {
        const int col = n0 + nwarp * 64 + nb * 8 + (lane & 3) * 2;
        float2 bv = *(const float2*)(bias + col);
#pragma unroll
        for (int mb = 0; mb < 2; ++mb)
#pragma unroll
            for (int rh = 0; rh < 2; ++rh) {
                int row = m0 + mwarp * 32 + mb * 16 + rh * 8 + (lane >> 2);
                float2 o = make_float2(acc[mb][nb][rh * 2] + bv.x,
                                       acc[mb][nb][rh * 2 + 1] + bv.y);
                *(float2*)(g_pre + (size_t)row * GG + col) = o;
            }
    }
}

// ---------------------------------------------------------------------------
// Kernel E: barrier init (every launch -> graph-replay safe)
// ---------------------------------------------------------------------------
__global__ void bar_init_kernel() {
    if (threadIdx.x < 128)
        ((unsigned*)g_bar4)[threadIdx.x] = 0u;
}

// ---------------------------------------------------------------------------
// Kernel F: persistent LSTM, int8 two-level quantized recurrent GEMM.
// Gates = s[g]/127 * (Qh_hi·Qu_hi + (Qh_hi·Qu_lo + Qh_lo·Qu_hi)/254) + pre.
// 128 CTAs (1/SM), per-mt barriers, K chunks of 128 bytes, IMMA k32.
// ---------------------------------------------------------------------------
__global__ __launch_bounds__(256, 1) void lstm_persistent(
    float* __restrict__ hidden,      // [B][T][H]
    float* __restrict__ c_state,     // [B][H]
    float* __restrict__ h_final) {   // [B][H]
    extern __shared__ char dsm[];
    const int tid = threadIdx.x;
    const int wid = tid >> 5;
    const int lane = tid & 31;
    const int jt = blockIdx.x;       // 0..31
    const int mt = blockIdx.y;       // 0..3
    const int mwarp = wid >> 1;      // 0..3
    const int jwarp = wid & 1;       // 0..1
    const uint32_t smem0 = (uint32_t)__cvta_generic_to_shared(dsm);

    // per-thread column scales: k1 = s[g-row]/127 for the 16 owned columns
    float k1s[4][2][2];
#pragma unroll
    for (int g = 0; g < 4; ++g)
#pragma unroll
        for (int nb = 0; nb < 2; ++nb)
#pragma unroll
            for (int e = 0; e < 2; ++e) {
                int col = jt * 32 + jwarp * 16 + nb * 8 + (lane & 3) * 2 + e;
                k1s[g][nb][e] = g_uscale[g * HH + col] * (1.0f / 127.0f);
            }

    // B loader: U^T int8 rows for this jt (step-independent addresses)
    auto issue_B = [&](int c, int s) {
        const int k0 = c * KCB;
        const uint32_t sb = smem0 + B_BASE + s * B_STAGE;
#pragma unroll
        for (int i = 0; i < 8; ++i) {
            int idx = i * 256 + tid;
            int mat = idx >> 10;
            int row = (idx >> 3) & 127;
            int gk = idx & 7;
            int grow = (row >> 5) * HH + jt * 32 + (row & 31);
            const signed char* src = (mat ? g_uq_lo : g_uq_hi) +
                (size_t)grow * HH + k0 + gk * 16;
            uint32_t dst = sb + mat * 16384 + row * 128 + ((gk ^ (row & 7)) << 4);
            cp_async16(dst, src);
        }
    };
    auto issue_pre = [&](int t) {
#pragma unroll
        for (int i = 0; i < 8; ++i) {
            int idx = i * 256 + tid;
            int row = idx >> 5;
            int gate = (idx >> 3) & 3;
            int g16 = idx & 7;
            const float* src = g_pre + ((size_t)(mt * 64 + row) * TT + t) * GG +
                               gate * HH + jt * 32 + g16 * 4;
            uint32_t dst = smem0 + PRE_BASE + row * PRE_ROW + gate * 128 + g16 * 16;
            cp_async16(dst, src);
        }
    };

    for (int t = 0; t < TT; ++t) {
        int hh[4][2][4];                 // hi*hi, s32
        int cr[4][2][4];                 // hi*lo + lo*hi, s32
#pragma unroll
        for (int g = 0; g < 4; ++g)
#pragma unroll
            for (int nb = 0; nb < 2; ++nb)
#pragma unroll
                for (int r = 0; r < 4; ++r) { hh[g][nb][r] = 0; cr[g][nb][r] = 0; }

        if (t > 0) {
            const signed char* hqhi = g_hq_hi[(t - 1) & 1];
            const signed char* hqlo = g_hq_lo[(t - 1) & 1];

            auto issue_A = [&](int c, int s) {
                const int k0 = c * KCB;
                const uint32_t sb = smem0 + s * A_STAGE;
#pragma unroll
                for (int i = 0; i < 4; ++i) {
                    int idx = i * 256 + tid;
                    int mat = idx >> 9;
                    int row = (idx >> 3) & 63;
                    int gk = idx & 7;
                    const signed char* src = (mat ? hqlo : hqhi) +
                        (size_t)(mt * 64 + row) * HH + k0 + gk * 16;
                    uint32_t dst = sb + mat * 8192 + row * 128 + ((gk ^ (row & 7)) << 4);
                    cp_async16(dst, src);
                }
            };

            // A chunk 0 (B chunk 0 prefetched across the step boundary).
            issue_A(0, 0);
            asm volatile("cp.async.commit_group;" ::: "memory");
            asm volatile("cp.async.wait_group 0;" ::: "memory");
            __syncthreads();

            const uint32_t arow = mwarp * 16 + (lane & 15);
            const uint32_t brow_base = jwarp * 16 + (lane & 7) + (lane >> 4) * 8;

            for (int c = 0; c < NCH; ++c) {
                const int s = c & 1;
                if (c + 1 < NCH) {
                    issue_A(c + 1, s ^ 1);
                    issue_B(c + 1, s ^ 1);
                    if (c == 1) issue_pre(t);
                } else if (t + 1 < TT) {
                    issue_B(0, 0);    // next step's first B chunk
                }
                asm volatile("cp.async.commit_group;" ::: "memory");

                const uint32_t sA = smem0 + s * A_STAGE;
                const uint32_t sB = smem0 + B_BASE + s * B_STAGE;
#pragma unroll
                for (int ks = 0; ks < 4; ++ks) {     // 4 x k32 per 128B chunk
                    uint32_t a_hi[4], a_lo[4];
                    {
                        int gk = ks * 2 + (lane >> 4);
                        uint32_t off = arow * 128 + ((gk ^ (arow & 7)) << 4);
                        ldsm_x4(a_hi, sA + off);
                        ldsm_x4(a_lo, sA + 8192 + off);
                    }
#pragma unroll
                    for (int g = 0; g < 4; ++g) {
                        uint32_t row = g * 32 + brow_base;
                        int gk = ks * 2 + ((lane >> 3) & 1);
                        uint32_t off = row * 128 + ((gk ^ (row & 7)) << 4);
                        uint32_t b_hi4[4], b_lo4[4];
                        ldsm_x4(b_hi4, sB + off);
                        ldsm_x4(b_lo4, sB + 16384 + off);
#pragma unroll
                        for (int nb = 0; nb < 2; ++nb) {
                            mma_s8(hh[g][nb], a_hi, b_hi4[nb * 2], b_hi4[nb * 2 + 1]);
                            mma_s8(cr[g][nb], a_hi, b_lo4[nb * 2], b_lo4[nb * 2 + 1]);
                            mma_s8(cr[g][nb], a_lo, b_hi4[nb * 2], b_hi4[nb * 2 + 1]);
                        }
                    }
                }
                if (c + 1 < NCH) {
                    asm volatile("cp.async.wait_group 0;" ::: "memory");
                    __syncthreads();
                }
            }
        } else {
            // t == 0: prefetch B chunk 0 for step 1 + pre tile for t=0.
            issue_B(0, 0);
            issue_pre(0);
            asm volatile("cp.async.commit_group;" ::: "memory");
            asm volatile("cp.async.wait_group 0;" ::: "memory");
            __syncthreads();
        }

        // ---- fused cell-update epilogue (pre from smem; merge scales) ----
        const int b_base = mt * 64 + mwarp * 16 + (lane >> 2);
#pragma unroll
        for (int rh = 0; rh < 2; ++rh) {
            const int b = b_base + rh * 8;
            const char* prs = dsm + PRE_BASE +
                (size_t)(mwarp * 16 + rh * 8 + (lane >> 2)) * PRE_ROW;
            float* crow = c_state + (size_t)b * HH;
            float* hrow = hidden + ((size_t)b * TT + t) * HH;
            signed char* bh = g_hq_hi[t & 1] + (size_t)b * HH;
            signed char* bl = g_hq_lo[t & 1] + (size_t)b * HH;
#pragma unroll
            for (int nb = 0; nb < 2; ++nb) {
                const int jcol = jwarp * 16 + nb * 8 + (lane & 3) * 2;
                const int j = jt * 32 + jcol;
                float2 pi = *(const float2*)(prs + 0 * 128 + jcol * 4);
                float2 pf = *(const float2*)(prs + 1 * 128 + jcol * 4);
                float2 pg = *(const float2*)(prs + 2 * 128 + jcol * 4);
                float2 po = *(const float2*)(prs + 3 * 128 + jcol * 4);
                float2 co = (t > 0) ? *(const float2*)(crow + j)
                                    : make_float2(0.f, 0.f);
                const int r0 = rh * 2;
                const float IR = 1.0f / 254.0f;
#define GATEV(G, E) (fmaf((float)cr[G][nb][r0 + E], IR, \
                          (float)hh[G][nb][r0 + E]) * k1s[G][nb][E])
                float i0 = fast_sigmoid(GATEV(0, 0) + pi.x);
                float i1 = fast_sigmoid(GATEV(0, 1) + pi.y);
                float f0 = fast_sigmoid(GATEV(1, 0) + pf.x);
                float f1 = fast_sigmoid(GATEV(1, 1) + pf.y);
                float g0 = fast_tanh(GATEV(2, 0) + pg.x);
                float g1 = fast_tanh(GATEV(2, 1) + pg.y);
                float o0 = fast_sigmoid(GATEV(3, 0) + po.x);
                float o1 = fast_sigmoid(GATEV(3, 1) + po.y);
#undef GATEV
                float cn0 = f0 * co.x + i0 * g0;
                float cn1 = f1 * co.y + i1 * g1;
                float hn0 = o0 * fast_tanh(cn0);
                float hn1 = o1 * fast_tanh(cn1);
                *(float2*)(crow + j) = make_float2(cn0, cn1);
                *(float2*)(hrow + j) = make_float2(hn0, hn1);
                // two-level int8 quantization of h for next step
                int q0 = __float2int_rn(hn0 * 127.0f);
                int q1 = __float2int_rn(hn1 * 127.0f);
                float rr0 = fmaf(hn0, 127.0f, -(float)q0);
                float rr1 = fmaf(hn1, 127.0f, -(float)q1);
                int ql0 = __float2int_rn(rr0 * 254.0f);
                int ql1 = __float2int_rn(rr1 * 254.0f);
                *(char2*)(bh + j) = make_char2((signed char)q0, (signed char)q1);
                *(char2*)(bl + j) = make_char2((signed char)ql0, (signed char)ql1);
                if (t == TT - 1)
                    *(float2*)(h_final + (size_t)b * HH + j) = make_float2(hn0, hn1);
            }
        }

        // ---- per-mt device barrier (32 CTAs) ----
        if (t < TT - 1) {
            __threadfence();
            __syncthreads();
            if (tid == 0) {
                atomicAdd(&g_bar4[mt][0], 1u);
                const unsigned target = 32u * (unsigned)(t + 1);
                while (atomicAdd(&g_bar4[mt][0], 0u) < target) {}
            }
            __syncthreads();
            __threadfence();
        }
    }
}

// ---------------------------------------------------------------------------
// Kernel G: y_pred[b] = h_final[b,:] . fc_w + fc_b
// ---------------------------------------------------------------------------
__global__ void fc_kernel(const float* __restrict__ h_final,
                          const float* __restrict__ fc_w,
                          const float* __restrict__ fc_b,
                          float* __restrict__ y_pred) {
    int b = blockIdx.x;
    int tid = threadIdx.x;
    float s = 0.f;
    for (int k = tid; k < HH; k += 256)
        s += h_final[b * HH + k] * fc_w[k];
#pragma unroll
    for (int off = 16; off > 0; off >>= 1)
        s += __shfl_down_sync(0xffffffffu, s, off);
    __shared__ float red[8];
    if ((tid & 31) == 0) red[tid >> 5] = s;
    __syncthreads();
    if (tid == 0) {
        float tot = 0.f;
#pragma unroll
        for (int w = 0; w < 8; ++w) tot += red[w];
        y_pred[b] = tot + fc_b[0];
    }
}

// ---------------------------------------------------------------------------
extern "C" void kernel_launch(void* const* d_in, const int* in_sizes, int n_in,
                              void* d_out, int out_size) {
    const float* X    = (const float*)d_in[0];
    const float* W    = (const float*)d_in[1];
    const float* U    = (const float*)d_in[2];
    const float* bias = (const float*)d_in[3];
    const float* Wy   = (const float*)d_in[4];
    const float* fc_w = (const float*)d_in[5];
    const float* fc_b = (const float*)d_in[6];

    float* out = (float*)d_out;
    // output layout: y_pred[256] | hidden_seq[B*T*H] | h_t[B*H] | c_t[B*H]
    float* y_pred  = out;
    float* hidden  = out + 256;
    float* h_final = hidden + (size_t)BB * TT * HH;
    float* c_state = h_final + (size_t)BB * HH;

    cudaFuncSetAttribute(lstm_persistent, cudaFuncAttributeMaxDynamicSharedMemorySize,
                         DYN_SMEM);
    cudaFuncSetAttribute(pre_gemm_mma, cudaFuncAttributeMaxDynamicSharedMemorySize,
                         PRE_SMEM);

    wt_split_kernel<<<dim3(ID / 32, GG / 32), 256>>>(W, Wy);
    u_scale_kernel<<<GG / 32, 256>>>(U);
    u_quant_kernel<<<dim3(HH / 32, GG / 32), 256>>>(U);
    x_split_kernel<<<(BB * TT * ID) / 4 / 256, 256>>>(X);
    pre_gemm_mma<<<dim3(GG / 128, (BB * TT) / 128), 256, PRE_SMEM>>>(bias);
    bar_init_kernel<<<1, 128>>>();
    lstm_persistent<<<dim3(HH / 32, BB / 64), 256, DYN_SMEM>>>(hidden, c_state,
                                                               h_final);
    fc_kernel<<<BB, 256>>>(h_final, fc_w, fc_b, y_pred);
}

// round 11
// speedup vs baseline: 2.8731x; 2.8731x over previous
#include <cuda_runtime.h>
#include <cuda_bf16.h>
#include <cuda_fp16.h>
#include <math.h>
#include <stdint.h>

// Problem constants
#define BB   256      // batch
#define TT   256      // time steps
#define ID   256      // input dim
#define HH   1024     // hidden dim
#define GG   4096     // 4*H gates

// Step-kernel tiling (fp16 2-pass): KC = 64 fp16 elements (128B rows)
#define KC          64
#define NCH         (HH / KC)          // 16 chunks
#define A_STAGE     16384              // h: hi 8K + lo 8K
#define B_BASE      32768
#define B_STAGE     16384              // U: single fp16 mat, 128 rows x 128B
#define PRE_BASE    65536
#define PRE_ROW     544                // 512 data + 32 pad
#define DYN_SMEM    (PRE_BASE + 64 * PRE_ROW)   // 100,352
// Pre-GEMM smem: single stage, Ahi/Alo 16K + Bhi/Blo 16K
#define PRE_SMEM    65536

typedef unsigned long long ull;

// Scratch (device globals: allocation-free rule)
__device__ float g_pre[(size_t)BB * TT * GG];        // 1 GiB input-gate precompute
__device__ __half g_ut[(size_t)GG * HH];             // U^T fp16 [4096][1024]
__device__ __nv_bfloat16 g_wt_hi[GG * ID];           // folded W^T bf16 split hi
__device__ __nv_bfloat16 g_wt_lo[GG * ID];           // folded W^T bf16 split lo
__device__ __nv_bfloat16 g_x_hi[(size_t)BB * TT * ID];   // X bf16 split hi
__device__ __nv_bfloat16 g_x_lo[(size_t)BB * TT * ID];   // X bf16 split lo
__device__ __half g_h_hi[2][BB * HH];                // h ping-pong fp16 hi
__device__ __half g_h_lo[2][BB * HH];                // h ping-pong fp16 lo
__device__ __align__(128) unsigned g_bar4[4][32];    // per-mt barriers (padded)

// ---------------------------------------------------------------------------
// helpers
// ---------------------------------------------------------------------------
__device__ __forceinline__ float fast_sigmoid(float x) {
    float e = __expf(-x);
    return __fdividef(1.0f, 1.0f + e);
}
__device__ __forceinline__ float fast_tanh(float x) {
    float e = __expf(2.0f * x);
    return 1.0f - __fdividef(2.0f, e + 1.0f);
}
__device__ __forceinline__ void cp_async16(uint32_t dst, const void* src) {
    asm volatile("cp.async.cg.shared.global [%0], [%1], 16;" :: "r"(dst), "l"(src));
}
__device__ __forceinline__ void ldsm_x4(uint32_t* r, uint32_t addr) {
    asm volatile("ldmatrix.sync.aligned.m8n8.x4.shared.b16 {%0,%1,%2,%3}, [%4];"
                 : "=r"(r[0]), "=r"(r[1]), "=r"(r[2]), "=r"(r[3]) : "r"(addr));
}
// bf16 x bf16 -> f32 accum (pre-GEMM)
__device__ __forceinline__ void mma_bf16(float* d, const uint32_t* a, const uint32_t* b) {
    asm volatile("mma.sync.aligned.m16n8k16.row.col.f32.bf16.bf16.f32 "
                 "{%0,%1,%2,%3}, {%4,%5,%6,%7}, {%8,%9}, {%0,%1,%2,%3};"
                 : "+f"(d[0]), "+f"(d[1]), "+f"(d[2]), "+f"(d[3])
                 : "r"(a[0]), "r"(a[1]), "r"(a[2]), "r"(a[3]), "r"(b[0]), "r"(b[1]));
}
// f16 x f16 -> f32 accum (step kernel)
__device__ __forceinline__ void mma_f16_f32(float* d, const uint32_t* a, const uint32_t* b) {
    asm volatile("mma.sync.aligned.m16n8k16.row.col.f32.f16.f16.f32 "
                 "{%0,%1,%2,%3}, {%4,%5,%6,%7}, {%8,%9}, {%0,%1,%2,%3};"
                 : "+f"(d[0]), "+f"(d[1]), "+f"(d[2]), "+f"(d[3])
                 : "r"(a[0]), "r"(a[1]), "r"(a[2]), "r"(a[3]), "r"(b[0]), "r"(b[1]));
}

// ---------------------------------------------------------------------------
// Kernel A: fold Wy into W row 255, transpose, bf16-split -> g_wt_hi/lo[g][k]
// ---------------------------------------------------------------------------
__global__ void wt_split_kernel(const float* __restrict__ W,
                                const float* __restrict__ Wy) {
    __shared__ float tile[32][33];
    const int kb = blockIdx.x * 32;
    const int gb = blockIdx.y * 32;
    const int tx = threadIdx.x & 31;
    const int ty = threadIdx.x >> 5;
#pragma unroll
    for (int i = 0; i < 32; i += 8) {
        int krow = kb + ty + i;
        float v = W[(size_t)krow * GG + gb + tx];
        if (krow == ID - 1) v += Wy[gb + tx];
        tile[ty + i][tx] = v;
    }
    __syncthreads();
#pragma unroll
    for (int i = 0; i < 32; i += 8) {
        int g = gb + ty + i;
        int k = kb + tx;
        float v = tile[tx][ty + i];
        __nv_bfloat16 hi = __float2bfloat16(v);
        __nv_bfloat16 lo = __float2bfloat16(v - __bfloat162float(hi));
        g_wt_hi[g * ID + k] = hi;
        g_wt_lo[g * ID + k] = lo;
    }
}

// ---------------------------------------------------------------------------
// Kernel B: U^T fp16: g_ut[g][k] = fp16(U[k][g])
// ---------------------------------------------------------------------------
__global__ void u_split_kernel(const float* __restrict__ U) {
    __shared__ float tile[32][33];
    const int kb = blockIdx.x * 32;
    const int gb = blockIdx.y * 32;
    const int tx = threadIdx.x & 31;
    const int ty = threadIdx.x >> 5;
#pragma unroll
    for (int i = 0; i < 32; i += 8)
        tile[ty + i][tx] = U[(size_t)(kb + ty + i) * GG + gb + tx];
    __syncthreads();
#pragma unroll
    for (int i = 0; i < 32; i += 8) {
        int g = gb + ty + i;
        int k = kb + tx;
        g_ut[(size_t)g * HH + k] = __float2half_rn(tile[tx][ty + i]);
    }
}

// ---------------------------------------------------------------------------
// Kernel C: X bf16 split
// ---------------------------------------------------------------------------
__global__ void x_split_kernel(const float* __restrict__ X) {
    size_t i4 = (size_t)blockIdx.x * blockDim.x + threadIdx.x;
    float4 v = *(const float4*)(X + i4 * 4);
    float f[4] = {v.x, v.y, v.z, v.w};
    __nv_bfloat16 hi[4], lo[4];
#pragma unroll
    for (int e = 0; e < 4; ++e) {
        hi[e] = __float2bfloat16(f[e]);
        lo[e] = __float2bfloat16(f[e] - __bfloat162float(hi[e]));
    }
    *(__nv_bfloat162*)(g_x_hi + i4 * 4)     = __nv_bfloat162(hi[0], hi[1]);
    *(__nv_bfloat162*)(g_x_hi + i4 * 4 + 2) = __nv_bfloat162(hi[2], hi[3]);
    *(__nv_bfloat162*)(g_x_lo + i4 * 4)     = __nv_bfloat162(lo[0], lo[1]);
    *(__nv_bfloat162*)(g_x_lo + i4 * 4 + 2) = __nv_bfloat162(lo[2], lo[3]);
}

// ---------------------------------------------------------------------------
// Kernel D: tensorized pre-GEMM (occ-2, single stage, bf16 3-pass). Proven.
// ---------------------------------------------------------------------------
__global__ __launch_bounds__(256, 2) void pre_gemm_mma(
    const float* __restrict__ bias) {
    extern __shared__ char dsm[];
    const uint32_t sA = (uint32_t)__cvta_generic_to_shared(dsm);
    const uint32_t sB = sA + 32768;

    const int tid = threadIdx.x;
    const int wid = tid >> 5;
    const int lane = tid & 31;
    const int mwarp = wid >> 1;
    const int nwarp = wid & 1;
    const int m0 = blockIdx.y * 128;
    const int n0 = blockIdx.x * 128;

    float acc[2][8][4];
#pragma unroll
    for (int mb = 0; mb < 2; ++mb)
#pragma unroll
        for (int nb = 0; nb < 8; ++nb)
#pragma unroll
            for (int r = 0; r < 4; ++r) acc[mb][nb][r] = 0.f;

    for (int kb = 0; kb < ID / 64; ++kb) {
        const int k0 = kb * 64;
        __syncthreads();
#pragma unroll
        for (int i = 0; i < 8; ++i) {
            int idx = i * 256 + tid;
            int mat = idx >> 10;
            int row = (idx >> 3) & 127;
            int gk = idx & 7;
            const __nv_bfloat16* src = (mat ? g_x_lo : g_x_hi) +
                (size_t)(m0 + row) * ID + k0 + gk * 8;
            uint32_t dst = sA + mat * 16384 + row * 128 + ((gk ^ (row & 7)) << 4);
            cp_async16(dst, src);
        }
#pragma unroll
        for (int i = 0; i < 8; ++i) {
            int idx = i * 256 + tid;
            int mat = idx >> 10;
            int row = (idx >> 3) & 127;
            int gk = idx & 7;
            const __nv_bfloat16* src = (mat ? g_wt_lo : g_wt_hi) +
                (size_t)(n0 + row) * ID + k0 + gk * 8;
            uint32_t dst = sB + mat * 16384 + row * 128 + ((gk ^ (row & 7)) << 4);
            cp_async16(dst, src);
        }
        asm volatile("cp.async.commit_group;" ::: "memory");
        asm volatile("cp.async.wait_group 0;" ::: "memory");
        __syncthreads();

#pragma unroll
        for (int ks = 0; ks < 4; ++ks) {
            uint32_t a_hi[2][4], a_lo[2][4];
#pragma unroll
            for (int mb = 0; mb < 2; ++mb) {
                uint32_t arow = mwarp * 32 + mb * 16 + (lane & 15);
                int gk = ks * 2 + (lane >> 4);
                uint32_t off = arow * 128 + ((gk ^ (arow & 7)) << 4);
                ldsm_x4(a_hi[mb], sA + off);
                ldsm_x4(a_lo[mb], sA + 16384 + off);
            }
#pragma unroll
            for (int nbp = 0; nbp < 4; ++nbp) {
                uint32_t brow = nwarp * 64 + nbp * 16 + (lane & 7) + (lane >> 4) * 8;
                int gk = ks * 2 + ((lane >> 3) & 1);
                uint32_t off = brow * 128 + ((gk ^ (brow & 7)) << 4);
                uint32_t b_hi4[4], b_lo4[4];
                ldsm_x4(b_hi4, sB + off);
                ldsm_x4(b_lo4, sB + 16384 + off);
#pragma unroll
                for (int h = 0; h < 2; ++h) {
#pragma unroll
                    for (int mb = 0; mb < 2; ++mb) {
                        mma_bf16(acc[mb][nbp * 2 + h], a_hi[mb], b_hi4 + h * 2);
                        mma_bf16(acc[mb][nbp * 2 + h], a_hi[mb], b_lo4 + h * 2);
                        mma_bf16(acc[mb][nbp * 2 + h], a_lo[mb], b_hi4 + h * 2);
                    }
                }
            }
        }
    }

#pragma unroll
    for (int nb = 0; nb < 8; ++nb) {
        const int col = n0 + nwarp * 64 + nb * 8 + (lane & 3) * 2;
        float2 bv = *(const float2*)(bias + col);
#pragma unroll
        for (int mb = 0; mb < 2; ++mb)
#pragma unroll
            for (int rh = 0; rh < 2; ++rh) {
                int row = m0 + mwarp * 32 + mb * 16 + rh * 8 + (lane >> 2);
                float2 o = make_float2(acc[mb][nb][rh * 2] + bv.x,
                                       acc[mb][nb][rh * 2 + 1] + bv.y);
                *(float2*)(g_pre + (size_t)row * GG + col) = o;
            }
    }
}

// ---------------------------------------------------------------------------
// Kernel E: barrier init (every launch -> graph-replay safe)
// ---------------------------------------------------------------------------
__global__ void bar_init_kernel() {
    if (threadIdx.x < 128)
        ((unsigned*)g_bar4)[threadIdx.x] = 0u;
}

// ---------------------------------------------------------------------------
// Kernel F: persistent LSTM, fp16 2-pass: Gates = (h_hi + h_lo) @ U16 + pre.
// 128 CTAs (1/SM), per-mt barriers, decoupled A/B pipelines, B prefetched
// across step boundary, pre tile prefetched to smem during MMA loop.
// ---------------------------------------------------------------------------
__global__ __launch_bounds__(256, 1) void lstm_persistent(
    float* __restrict__ hidden,      // [B][T][H]
    float* __restrict__ c_state,     // [B][H]
    float* __restrict__ h_final) {   // [B][H]
    extern __shared__ char dsm[];
    const int tid = threadIdx.x;
    const int wid = tid >> 5;
    const int lane = tid & 31;
    const int jt = blockIdx.x;       // 0..31
    const int mt = blockIdx.y;       // 0..3
    const int mwarp = wid >> 1;      // 0..3
    const int jwarp = wid & 1;       // 0..1
    const uint32_t smem0 = (uint32_t)__cvta_generic_to_shared(dsm);

    // B loader: U^T fp16 rows for this jt (step-independent addresses)
    auto issue_B = [&](int c, int s) {
        const int k0 = c * KC;
        const uint32_t sb = smem0 + B_BASE + s * B_STAGE;
#pragma unroll
        for (int i = 0; i < 4; ++i) {
            int idx = i * 256 + tid;
            int row = idx >> 3;
            int gk = idx & 7;
            int grow = (row >> 5) * HH + jt * 32 + (row & 31);
            const __half* src = g_ut + (size_t)grow * HH + k0 + gk * 8;
            uint32_t dst = sb + row * 128 + ((gk ^ (row & 7)) << 4);
            cp_async16(dst, src);
        }
    };
    auto issue_pre = [&](int t) {
#pragma unroll
        for (int i = 0; i < 8; ++i) {
            int idx = i * 256 + tid;
            int row = idx >> 5;
            int gate = (idx >> 3) & 3;
            int g16 = idx & 7;
            const float* src = g_pre + ((size_t)(mt * 64 + row) * TT + t) * GG +
                               gate * HH + jt * 32 + g16 * 4;
            uint32_t dst = smem0 + PRE_BASE + row * PRE_ROW + gate * 128 + g16 * 16;
            cp_async16(dst, src);
        }
    };

    for (int t = 0; t < TT; ++t) {
        float acc[4][2][4];
#pragma unroll
        for (int g = 0; g < 4; ++g)
#pragma unroll
            for (int nb = 0; nb < 2; ++nb)
#pragma unroll
                for (int r = 0; r < 4; ++r) acc[g][nb][r] = 0.f;

        if (t > 0) {
            const __half* hphi = g_h_hi[(t - 1) & 1];
            const __half* hplo = g_h_lo[(t - 1) & 1];

            auto issue_A = [&](int c, int s) {
                const int k0 = c * KC;
                const uint32_t sb = smem0 + s * A_STAGE;
#pragma unroll
                for (int i = 0; i < 4; ++i) {
                    int idx = i * 256 + tid;
                    int mat = idx >> 9;
                    int row = (idx >> 3) & 63;
                    int gk = idx & 7;
                    const __half* src = (mat ? hplo : hphi) +
                        (size_t)(mt * 64 + row) * HH + k0 + gk * 8;
                    uint32_t dst = sb + mat * 8192 + row * 128 + ((gk ^ (row & 7)) << 4);
                    cp_async16(dst, src);
                }
            };

            // A chunk 0 (B chunk 0 prefetched across the step boundary;
            // its completion is covered by this wait_group 0 too).
            issue_A(0, 0);
            asm volatile("cp.async.commit_group;" ::: "memory");
            asm volatile("cp.async.wait_group 0;" ::: "memory");
            __syncthreads();

            const uint32_t arow = mwarp * 16 + (lane & 15);
            const uint32_t brow_base = jwarp * 16 + (lane & 7) + (lane >> 4) * 8;

            for (int c = 0; c < NCH; ++c) {
                const int s = c & 1;
                if (c + 1 < NCH) {
                    issue_A(c + 1, s ^ 1);
                    issue_B(c + 1, s ^ 1);
                    if (c == 1) issue_pre(t);
                } else if (t + 1 < TT) {
                    issue_B(0, 0);    // next step's first B chunk
                }
                asm volatile("cp.async.commit_group;" ::: "memory");

                const uint32_t sA = smem0 + s * A_STAGE;
                const uint32_t sB = smem0 + B_BASE + s * B_STAGE;
#pragma unroll
                for (int ks = 0; ks < KC / 16; ++ks) {
                    uint32_t a_hi[4], a_lo[4];
                    {
                        int gk = ks * 2 + (lane >> 4);
                        uint32_t off = arow * 128 + ((gk ^ (arow & 7)) << 4);
                        ldsm_x4(a_hi, sA + off);
                        ldsm_x4(a_lo, sA + 8192 + off);
                    }
#pragma unroll
                    for (int g = 0; g < 4; ++g) {
                        uint32_t row = g * 32 + brow_base;
                        int gk = ks * 2 + ((lane >> 3) & 1);
                        uint32_t off = row * 128 + ((gk ^ (row & 7)) << 4);
                        uint32_t b4[4];
                        ldsm_x4(b4, sB + off);
#pragma unroll
                        for (int nb = 0; nb < 2; ++nb) {
                            mma_f16_f32(acc[g][nb], a_hi, b4 + nb * 2);
                            mma_f16_f32(acc[g][nb], a_lo, b4 + nb * 2);
                        }
                    }
                }
                if (c + 1 < NCH) {
                    asm volatile("cp.async.wait_group 0;" ::: "memory");
                    __syncthreads();
                }
                // final chunk: skip wait — pending B prefetch completes during
                // the barrier spin; waited at next step's wait_group 0.
            }
        } else {
            // t == 0: prefetch B chunk 0 for step 1 + pre tile for t=0.
            issue_B(0, 0);
            issue_pre(0);
            asm volatile("cp.async.commit_group;" ::: "memory");
            asm volatile("cp.async.wait_group 0;" ::: "memory");
            __syncthreads();
        }

        // ---- fused cell-update epilogue (pre read from smem) ----
        const int b_base = mt * 64 + mwarp * 16 + (lane >> 2);
#pragma unroll
        for (int rh = 0; rh < 2; ++rh) {
            const int b = b_base + rh * 8;
            const char* prs = dsm + PRE_BASE +
                (size_t)(mwarp * 16 + rh * 8 + (lane >> 2)) * PRE_ROW;
            float* crow = c_state + (size_t)b * HH;
            float* hrow = hidden + ((size_t)b * TT + t) * HH;
            __half* bh = g_h_hi[t & 1] + (size_t)b * HH;
            __half* bl = g_h_lo[t & 1] + (size_t)b * HH;
#pragma unroll
            for (int nb = 0; nb < 2; ++nb) {
                const int jcol = jwarp * 16 + nb * 8 + (lane & 3) * 2;
                const int j = jt * 32 + jcol;
                float2 pi = *(const float2*)(prs + 0 * 128 + jcol * 4);
                float2 pf = *(const float2*)(prs + 1 * 128 + jcol * 4);
                float2 pg = *(const float2*)(prs + 2 * 128 + jcol * 4);
                float2 po = *(const float2*)(prs + 3 * 128 + jcol * 4);
                float2 co = (t > 0) ? *(const float2*)(crow + j)
                                    : make_float2(0.f, 0.f);
                const int r0 = rh * 2;
                float i0 = fast_sigmoid(acc[0][nb][r0]     + pi.x);
                float i1 = fast_sigmoid(acc[0][nb][r0 + 1] + pi.y);
                float f0 = fast_sigmoid(acc[1][nb][r0]     + pf.x);
                float f1 = fast_sigmoid(acc[1][nb][r0 + 1] + pf.y);
                float g0 = fast_tanh(acc[2][nb][r0]     + pg.x);
                float g1 = fast_tanh(acc[2][nb][r0 + 1] + pg.y);
                float o0 = fast_sigmoid(acc[3][nb][r0]     + po.x);
                float o1 = fast_sigmoid(acc[3][nb][r0 + 1] + po.y);
                float cn0 = f0 * co.x + i0 * g0;
                float cn1 = f1 * co.y + i1 * g1;
                float hn0 = o0 * fast_tanh(cn0);
                float hn1 = o1 * fast_tanh(cn1);
                *(float2*)(crow + j) = make_float2(cn0, cn1);
                *(float2*)(hrow + j) = make_float2(hn0, hn1);
                __half h0h = __float2half_rn(hn0);
                __half h1h = __float2half_rn(hn1);
                __half h0l = __float2half_rn(hn0 - __half2float(h0h));
                __half h1l = __float2half_rn(hn1 - __half2float(h1h));
                *(__half2*)(bh + j) = __halves2half2(h0h, h1h);
                *(__half2*)(bl + j) = __halves2half2(h0l, h1l);
                if (t == TT - 1)
                    *(float2*)(h_final + (size_t)b * HH + j) = make_float2(hn0, hn1);
            }
        }

        // ---- per-mt device barrier (32 CTAs) ----
        if (t < TT - 1) {
            __threadfence();
            __syncthreads();
            if (tid == 0) {
                atomicAdd(&g_bar4[mt][0], 1u);
                const unsigned target = 32u * (unsigned)(t + 1);
                while (atomicAdd(&g_bar4[mt][0], 0u) < target) {}
            }
            __syncthreads();
            __threadfence();
        }
    }
}

// ---------------------------------------------------------------------------
// Kernel G: y_pred[b] = h_final[b,:] . fc_w + fc_b
// ---------------------------------------------------------------------------
__global__ void fc_kernel(const float* __restrict__ h_final,
                          const float* __restrict__ fc_w,
                          const float* __restrict__ fc_b,
                          float* __restrict__ y_pred) {
    int b = blockIdx.x;
    int tid = threadIdx.x;
    float s = 0.f;
    for (int k = tid; k < HH; k += 256)
        s += h_final[b * HH + k] * fc_w[k];
#pragma unroll
    for (int off = 16; off > 0; off >>= 1)
        s += __shfl_down_sync(0xffffffffu, s, off);
    __shared__ float red[8];
    if ((tid & 31) == 0) red[tid >> 5] = s;
    __syncthreads();
    if (tid == 0) {
        float tot = 0.f;
#pragma unroll
        for (int w = 0; w < 8; ++w) tot += red[w];
        y_pred[b] = tot + fc_b[0];
    }
}

// ---------------------------------------------------------------------------
extern "C" void kernel_launch(void* const* d_in, const int* in_sizes, int n_in,
                              void* d_out, int out_size) {
    const float* X    = (const float*)d_in[0];
    const float* W    = (const float*)d_in[1];
    const float* U    = (const float*)d_in[2];
    const float* bias = (const float*)d_in[3];
    const float* Wy   = (const float*)d_in[4];
    const float* fc_w = (const float*)d_in[5];
    const float* fc_b = (const float*)d_in[6];

    float* out = (float*)d_out;
    // output layout: y_pred[256] | hidden_seq[B*T*H] | h_t[B*H] | c_t[B*H]
    float* y_pred  = out;
    float* hidden  = out + 256;
    float* h_final = hidden + (size_t)BB * TT * HH;
    float* c_state = h_final + (size_t)BB * HH;

    cudaFuncSetAttribute(lstm_persistent, cudaFuncAttributeMaxDynamicSharedMemorySize,
                         DYN_SMEM);
    cudaFuncSetAttribute(pre_gemm_mma, cudaFuncAttributeMaxDynamicSharedMemorySize,
                         PRE_SMEM);

    wt_split_kernel<<<dim3(ID / 32, GG / 32), 256>>>(W, Wy);
    u_split_kernel<<<dim3(HH / 32, GG / 32), 256>>>(U);
    x_split_kernel<<<(BB * TT * ID) / 4 / 256, 256>>>(X);
    pre_gemm_mma<<<dim3(GG / 128, (BB * TT) / 128), 256, PRE_SMEM>>>(bias);
    bar_init_kernel<<<1, 128>>>();
    lstm_persistent<<<dim3(HH / 32, BB / 64), 256, DYN_SMEM>>>(hidden, c_state,
                                                               h_final);
    fc_kernel<<<BB, 256>>>(h_final, fc_w, fc_b, y_pred);
}

// round 12
// speedup vs baseline: 3.5400x; 1.2321x over previous
#include <cuda_runtime.h>
#include <cuda_fp16.h>
#include <math.h>
#include <stdint.h>

// Problem constants
#define BB   256      // batch
#define TT   256      // time steps
#define ID   256      // input dim
#define HH   1024     // hidden dim
#define GG   4096     // 4*H gates

// Step-kernel tiling (fp16 single-pass): KC = 64 fp16 elements (128B rows)
#define KC          64
#define NCH         (HH / KC)          // 16 chunks
#define A_STAGE     8192               // h fp16: 64 rows x 128B
#define B_BASE      16384
#define B_STAGE     16384              // U fp16: 128 rows x 128B
#define PRE_BASE    49152
#define PRE_ROW     544                // 512 data + 32 pad
#define DYN_SMEM    (PRE_BASE + 64 * PRE_ROW)   // 83,968
// Pre-GEMM smem: Ahi 16K + Alo 16K + B 16K
#define PRE_SMEM    49152

typedef unsigned long long ull;

// Scratch (device globals: allocation-free rule)
__device__ float g_pre[(size_t)BB * TT * GG];        // 1 GiB input-gate precompute
__device__ __half g_ut[(size_t)GG * HH];             // U^T fp16 [4096][1024]
__device__ __half g_wt[GG * ID];                     // folded W^T fp16 [4096][256]
__device__ __half g_x_hi[(size_t)BB * TT * ID];      // X fp16 split hi
__device__ __half g_x_lo[(size_t)BB * TT * ID];      // X fp16 split lo
__device__ __half g_h[2][BB * HH];                   // h ping-pong fp16
__device__ __align__(128) unsigned g_bar4[4][32];    // per-mt barriers (padded)

// ---------------------------------------------------------------------------
// helpers
// ---------------------------------------------------------------------------
__device__ __forceinline__ float fast_sigmoid(float x) {
    float e = __expf(-x);
    return __fdividef(1.0f, 1.0f + e);
}
__device__ __forceinline__ float fast_tanh(float x) {
    float e = __expf(2.0f * x);
    return 1.0f - __fdividef(2.0f, e + 1.0f);
}
__device__ __forceinline__ void cp_async16(uint32_t dst, const void* src) {
    asm volatile("cp.async.cg.shared.global [%0], [%1], 16;" :: "r"(dst), "l"(src));
}
__device__ __forceinline__ void ldsm_x4(uint32_t* r, uint32_t addr) {
    asm volatile("ldmatrix.sync.aligned.m8n8.x4.shared.b16 {%0,%1,%2,%3}, [%4];"
                 : "=r"(r[0]), "=r"(r[1]), "=r"(r[2]), "=r"(r[3]) : "r"(addr));
}
// f16 x f16 -> f32 accum
__device__ __forceinline__ void mma_f16_f32(float* d, const uint32_t* a, const uint32_t* b) {
    asm volatile("mma.sync.aligned.m16n8k16.row.col.f32.f16.f16.f32 "
                 "{%0,%1,%2,%3}, {%4,%5,%6,%7}, {%8,%9}, {%0,%1,%2,%3};"
                 : "+f"(d[0]), "+f"(d[1]), "+f"(d[2]), "+f"(d[3])
                 : "r"(a[0]), "r"(a[1]), "r"(a[2]), "r"(a[3]), "r"(b[0]), "r"(b[1]));
}

// ---------------------------------------------------------------------------
// Kernel A: fold Wy into W row 255, transpose -> g_wt[g][k] fp16
// ---------------------------------------------------------------------------
__global__ void wt_split_kernel(const float* __restrict__ W,
                                const float* __restrict__ Wy) {
    __shared__ float tile[32][33];
    const int kb = blockIdx.x * 32;
    const int gb = blockIdx.y * 32;
    const int tx = threadIdx.x & 31;
    const int ty = threadIdx.x >> 5;
#pragma unroll
    for (int i = 0; i < 32; i += 8) {
        int krow = kb + ty + i;
        float v = W[(size_t)krow * GG + gb + tx];
        if (krow == ID - 1) v += Wy[gb + tx];
        tile[ty + i][tx] = v;
    }
    __syncthreads();
#pragma unroll
    for (int i = 0; i < 32; i += 8) {
        int g = gb + ty + i;
        int k = kb + tx;
        g_wt[g * ID + k] = __float2half_rn(tile[tx][ty + i]);
    }
}

// ---------------------------------------------------------------------------
// Kernel B: U^T fp16: g_ut[g][k] = fp16(U[k][g])
// ---------------------------------------------------------------------------
__global__ void u_split_kernel(const float* __restrict__ U) {
    __shared__ float tile[32][33];
    const int kb = blockIdx.x * 32;
    const int gb = blockIdx.y * 32;
    const int tx = threadIdx.x & 31;
    const int ty = threadIdx.x >> 5;
#pragma unroll
    for (int i = 0; i < 32; i += 8)
        tile[ty + i][tx] = U[(size_t)(kb + ty + i) * GG + gb + tx];
    __syncthreads();
#pragma unroll
    for (int i = 0; i < 32; i += 8) {
        int g = gb + ty + i;
        int k = kb + tx;
        g_ut[(size_t)g * HH + k] = __float2half_rn(tile[tx][ty + i]);
    }
}

// ---------------------------------------------------------------------------
// Kernel C: X fp16 split (hi + lo residual)
// ---------------------------------------------------------------------------
__global__ void x_split_kernel(const float* __restrict__ X) {
    size_t i4 = (size_t)blockIdx.x * blockDim.x + threadIdx.x;
    float4 v = *(const float4*)(X + i4 * 4);
    float f[4] = {v.x, v.y, v.z, v.w};
    __half hi[4], lo[4];
#pragma unroll
    for (int e = 0; e < 4; ++e) {
        hi[e] = __float2half_rn(f[e]);
        lo[e] = __float2half_rn(f[e] - __half2float(hi[e]));
    }
    *(__half2*)(g_x_hi + i4 * 4)     = __halves2half2(hi[0], hi[1]);
    *(__half2*)(g_x_hi + i4 * 4 + 2) = __halves2half2(hi[2], hi[3]);
    *(__half2*)(g_x_lo + i4 * 4)     = __halves2half2(lo[0], lo[1]);
    *(__half2*)(g_x_lo + i4 * 4 + 2) = __halves2half2(lo[2], lo[3]);
}

// ---------------------------------------------------------------------------
// Kernel D: tensorized pre-GEMM, fp16 2-pass: pre = (Xhi+Xlo)@W16 + bias.
// CTA 128m x 128n, occ 2, single-stage smem, 4 K-chunks of 64.
// ---------------------------------------------------------------------------
__global__ __launch_bounds__(256, 2) void pre_gemm_mma(
    const float* __restrict__ bias) {
    extern __shared__ char dsm[];
    const uint32_t sA = (uint32_t)__cvta_generic_to_shared(dsm);   // hi 16K | lo 16K
    const uint32_t sB = sA + 32768;                                 // 16K

    const int tid = threadIdx.x;
    const int wid = tid >> 5;
    const int lane = tid & 31;
    const int mwarp = wid >> 1;
    const int nwarp = wid & 1;
    const int m0 = blockIdx.y * 128;
    const int n0 = blockIdx.x * 128;

    float acc[2][8][4];
#pragma unroll
    for (int mb = 0; mb < 2; ++mb)
#pragma unroll
        for (int nb = 0; nb < 8; ++nb)
#pragma unroll
            for (int r = 0; r < 4; ++r) acc[mb][nb][r] = 0.f;

    for (int kb = 0; kb < ID / 64; ++kb) {
        const int k0 = kb * 64;
        __syncthreads();
        // A: 2 mats (hi/lo) x 128 rows x 8 granules = 2048 -> 8/thread
#pragma unroll
        for (int i = 0; i < 8; ++i) {
            int idx = i * 256 + tid;
            int mat = idx >> 10;
            int row = (idx >> 3) & 127;
            int gk = idx & 7;
            const __half* src = (mat ? g_x_lo : g_x_hi) +
                (size_t)(m0 + row) * ID + k0 + gk * 8;
            uint32_t dst = sA + mat * 16384 + row * 128 + ((gk ^ (row & 7)) << 4);
            cp_async16(dst, src);
        }
        // B: 1 mat x 128 rows x 8 granules = 1024 -> 4/thread
#pragma unroll
        for (int i = 0; i < 4; ++i) {
            int idx = i * 256 + tid;
            int row = idx >> 3;
            int gk = idx & 7;
            const __half* src = g_wt + (size_t)(n0 + row) * ID + k0 + gk * 8;
            uint32_t dst = sB + row * 128 + ((gk ^ (row & 7)) << 4);
            cp_async16(dst, src);
        }
        asm volatile("cp.async.commit_group;" ::: "memory");
        asm volatile("cp.async.wait_group 0;" ::: "memory");
        __syncthreads();

#pragma unroll
        for (int ks = 0; ks < 4; ++ks) {
            uint32_t a_hi[2][4], a_lo[2][4];
#pragma unroll
            for (int mb = 0; mb < 2; ++mb) {
                uint32_t arow = mwarp * 32 + mb * 16 + (lane & 15);
                int gk = ks * 2 + (lane >> 4);
                uint32_t off = arow * 128 + ((gk ^ (arow & 7)) << 4);
                ldsm_x4(a_hi[mb], sA + off);
                ldsm_x4(a_lo[mb], sA + 16384 + off);
            }
#pragma unroll
            for (int nbp = 0; nbp < 4; ++nbp) {
                uint32_t brow = nwarp * 64 + nbp * 16 + (lane & 7) + (lane >> 4) * 8;
                int gk = ks * 2 + ((lane >> 3) & 1);
                uint32_t off = brow * 128 + ((gk ^ (brow & 7)) << 4);
                uint32_t b4[4];
                ldsm_x4(b4, sB + off);
#pragma unroll
                for (int h = 0; h < 2; ++h) {
#pragma unroll
                    for (int mb = 0; mb < 2; ++mb) {
                        mma_f16_f32(acc[mb][nbp * 2 + h], a_hi[mb], b4 + h * 2);
                        mma_f16_f32(acc[mb][nbp * 2 + h], a_lo[mb], b4 + h * 2);
                    }
                }
            }
        }
    }

#pragma unroll
    for (int nb = 0; nb < 8; ++nb) {
        const int col = n0 + nwarp * 64 + nb * 8 + (lane & 3) * 2;
        float2 bv = *(const float2*)(bias + col);
#pragma unroll
        for (int mb = 0; mb < 2; ++mb)
#pragma unroll
            for (int rh = 0; rh < 2; ++rh) {
                int row = m0 + mwarp * 32 + mb * 16 + rh * 8 + (lane >> 2);
                float2 o = make_float2(acc[mb][nb][rh * 2] + bv.x,
                                       acc[mb][nb][rh * 2 + 1] + bv.y);
                *(float2*)(g_pre + (size_t)row * GG + col) = o;
            }
    }
}

// ---------------------------------------------------------------------------
// Kernel E: barrier init (every launch -> graph-replay safe)
// ---------------------------------------------------------------------------
__global__ void bar_init_kernel() {
    if (threadIdx.x < 128)
        ((unsigned*)g_bar4)[threadIdx.x] = 0u;
}

// ---------------------------------------------------------------------------
// Kernel F: persistent LSTM, fp16 single-pass: Gates = h16 @ U16 + pre.
// 128 CTAs (1/SM), per-mt barriers, decoupled A/B pipelines, B prefetched
// across step boundary, pre tile prefetched to smem during MMA loop.
// ---------------------------------------------------------------------------
__global__ __launch_bounds__(256, 1) void lstm_persistent(
    float* __restrict__ hidden,      // [B][T][H]
    float* __restrict__ c_state,     // [B][H]
    float* __restrict__ h_final) {   // [B][H]
    extern __shared__ char dsm[];
    const int tid = threadIdx.x;
    const int wid = tid >> 5;
    const int lane = tid & 31;
    const int jt = blockIdx.x;       // 0..31
    const int mt = blockIdx.y;       // 0..3
    const int mwarp = wid >> 1;      // 0..3
    const int jwarp = wid & 1;       // 0..1
    const uint32_t smem0 = (uint32_t)__cvta_generic_to_shared(dsm);

    // B loader: U^T fp16 rows for this jt (step-independent addresses)
    auto issue_B = [&](int c, int s) {
        const int k0 = c * KC;
        const uint32_t sb = smem0 + B_BASE + s * B_STAGE;
#pragma unroll
        for (int i = 0; i < 4; ++i) {
            int idx = i * 256 + tid;
            int row = idx >> 3;
            int gk = idx & 7;
            int grow = (row >> 5) * HH + jt * 32 + (row & 31);
            const __half* src = g_ut + (size_t)grow * HH + k0 + gk * 8;
            uint32_t dst = sb + row * 128 + ((gk ^ (row & 7)) << 4);
            cp_async16(dst, src);
        }
    };
    auto issue_pre = [&](int t) {
#pragma unroll
        for (int i = 0; i < 8; ++i) {
            int idx = i * 256 + tid;
            int row = idx >> 5;
            int gate = (idx >> 3) & 3;
            int g16 = idx & 7;
            const float* src = g_pre + ((size_t)(mt * 64 + row) * TT + t) * GG +
                               gate * HH + jt * 32 + g16 * 4;
            uint32_t dst = smem0 + PRE_BASE + row * PRE_ROW + gate * 128 + g16 * 16;
            cp_async16(dst, src);
        }
    };

    for (int t = 0; t < TT; ++t) {
        float acc[4][2][4];
#pragma unroll
        for (int g = 0; g < 4; ++g)
#pragma unroll
            for (int nb = 0; nb < 2; ++nb)
#pragma unroll
                for (int r = 0; r < 4; ++r) acc[g][nb][r] = 0.f;

        if (t > 0) {
            const __half* hp = g_h[(t - 1) & 1];

            auto issue_A = [&](int c, int s) {
                const int k0 = c * KC;
                const uint32_t sb = smem0 + s * A_STAGE;
#pragma unroll
                for (int i = 0; i < 2; ++i) {
                    int idx = i * 256 + tid;
                    int row = idx >> 3;
                    int gk = idx & 7;
                    const __half* src = hp + (size_t)(mt * 64 + row) * HH + k0 + gk * 8;
                    uint32_t dst = sb + row * 128 + ((gk ^ (row & 7)) << 4);
                    cp_async16(dst, src);
                }
            };

            // A chunk 0 (B chunk 0 prefetched across the step boundary;
            // its completion is covered by this wait_group 0 too).
            issue_A(0, 0);
            asm volatile("cp.async.commit_group;" ::: "memory");
            asm volatile("cp.async.wait_group 0;" ::: "memory");
            __syncthreads();

            const uint32_t arow = mwarp * 16 + (lane & 15);
            const uint32_t brow_base = jwarp * 16 + (lane & 7) + (lane >> 4) * 8;

            for (int c = 0; c < NCH; ++c) {
                const int s = c & 1;
                if (c + 1 < NCH) {
                    issue_A(c + 1, s ^ 1);
                    issue_B(c + 1, s ^ 1);
                    if (c == 1) issue_pre(t);
                } else if (t + 1 < TT) {
                    issue_B(0, 0);    // next step's first B chunk
                }
                asm volatile("cp.async.commit_group;" ::: "memory");

                const uint32_t sA = smem0 + s * A_STAGE;
                const uint32_t sB = smem0 + B_BASE + s * B_STAGE;
#pragma unroll
                for (int ks = 0; ks < KC / 16; ++ks) {
                    uint32_t a4[4];
                    {
                        int gk = ks * 2 + (lane >> 4);
                        uint32_t off = arow * 128 + ((gk ^ (arow & 7)) << 4);
                        ldsm_x4(a4, sA + off);
                    }
#pragma unroll
                    for (int g = 0; g < 4; ++g) {
                        uint32_t row = g * 32 + brow_base;
                        int gk = ks * 2 + ((lane >> 3) & 1);
                        uint32_t off = row * 128 + ((gk ^ (row & 7)) << 4);
                        uint32_t b4[4];
                        ldsm_x4(b4, sB + off);
                        mma_f16_f32(acc[g][0], a4, b4);
                        mma_f16_f32(acc[g][1], a4, b4 + 2);
                    }
                }
                if (c + 1 < NCH) {
                    asm volatile("cp.async.wait_group 0;" ::: "memory");
                    __syncthreads();
                }
                // final chunk: skip wait — pending B prefetch completes during
                // the barrier spin; waited at next step's wait_group 0.
            }
        } else {
            // t == 0: prefetch B chunk 0 for step 1 + pre tile for t=0.
            issue_B(0, 0);
            issue_pre(0);
            asm volatile("cp.async.commit_group;" ::: "memory");
            asm volatile("cp.async.wait_group 0;" ::: "memory");
            __syncthreads();
        }

        // ---- fused cell-update epilogue (pre read from smem) ----
        const int b_base = mt * 64 + mwarp * 16 + (lane >> 2);
#pragma unroll
        for (int rh = 0; rh < 2; ++rh) {
            const int b = b_base + rh * 8;
            const char* prs = dsm + PRE_BASE +
                (size_t)(mwarp * 16 + rh * 8 + (lane >> 2)) * PRE_ROW;
            float* crow = c_state + (size_t)b * HH;
            float* hrow = hidden + ((size_t)b * TT + t) * HH;
            __half* bh = g_h[t & 1] + (size_t)b * HH;
#pragma unroll
            for (int nb = 0; nb < 2; ++nb) {
                const int jcol = jwarp * 16 + nb * 8 + (lane & 3) * 2;
                const int j = jt * 32 + jcol;
                float2 pi = *(const float2*)(prs + 0 * 128 + jcol * 4);
                float2 pf = *(const float2*)(prs + 1 * 128 + jcol * 4);
                float2 pg = *(const float2*)(prs + 2 * 128 + jcol * 4);
                float2 po = *(const float2*)(prs + 3 * 128 + jcol * 4);
                float2 co = (t > 0) ? *(const float2*)(crow + j)
                                    : make_float2(0.f, 0.f);
                const int r0 = rh * 2;
                float i0 = fast_sigmoid(acc[0][nb][r0]     + pi.x);
                float i1 = fast_sigmoid(acc[0][nb][r0 + 1] + pi.y);
                float f0 = fast_sigmoid(acc[1][nb][r0]     + pf.x);
                float f1 = fast_sigmoid(acc[1][nb][r0 + 1] + pf.y);
                float g0 = fast_tanh(acc[2][nb][r0]     + pg.x);
                float g1 = fast_tanh(acc[2][nb][r0 + 1] + pg.y);
                float o0 = fast_sigmoid(acc[3][nb][r0]     + po.x);
                float o1 = fast_sigmoid(acc[3][nb][r0 + 1] + po.y);
                float cn0 = f0 * co.x + i0 * g0;
                float cn1 = f1 * co.y + i1 * g1;
                float hn0 = o0 * fast_tanh(cn0);
                float hn1 = o1 * fast_tanh(cn1);
                *(float2*)(crow + j) = make_float2(cn0, cn1);
                *(float2*)(hrow + j) = make_float2(hn0, hn1);
                *(__half2*)(bh + j) = __halves2half2(__float2half_rn(hn0),
                                                     __float2half_rn(hn1));
                if (t == TT - 1)
                    *(float2*)(h_final + (size_t)b * HH + j) = make_float2(hn0, hn1);
            }
        }

        // ---- per-mt device barrier (32 CTAs) ----
        if (t < TT - 1) {
            __threadfence();
            __syncthreads();
            if (tid == 0) {
                atomicAdd(&g_bar4[mt][0], 1u);
                const unsigned target = 32u * (unsigned)(t + 1);
                while (atomicAdd(&g_bar4[mt][0], 0u) < target) {}
            }
            __syncthreads();
            __threadfence();
        }
    }
}

// ---------------------------------------------------------------------------
// Kernel G: y_pred[b] = h_final[b,:] . fc_w + fc_b
// ---------------------------------------------------------------------------
__global__ void fc_kernel(const float* __restrict__ h_final,
                          const float* __restrict__ fc_w,
                          const float* __restrict__ fc_b,
                          float* __restrict__ y_pred) {
    int b = blockIdx.x;
    int tid = threadIdx.x;
    float s = 0.f;
    for (int k = tid; k < HH; k += 256)
        s += h_final[b * HH + k] * fc_w[k];
#pragma unroll
    for (int off = 16; off > 0; off >>= 1)
        s += __shfl_down_sync(0xffffffffu, s, off);
    __shared__ float red[8];
    if ((tid & 31) == 0) red[tid >> 5] = s;
    __syncthreads();
    if (tid == 0) {
        float tot = 0.f;
#pragma unroll
        for (int w = 0; w < 8; ++w) tot += red[w];
        y_pred[b] = tot + fc_b[0];
    }
}

// ---------------------------------------------------------------------------
extern "C" void kernel_launch(void* const* d_in, const int* in_sizes, int n_in,
                              void* d_out, int out_size) {
    const float* X    = (const float*)d_in[0];
    const float* W    = (const float*)d_in[1];
    const float* U    = (const float*)d_in[2];
    const float* bias = (const float*)d_in[3];
    const float* Wy   = (const float*)d_in[4];
    const float* fc_w = (const float*)d_in[5];
    const float* fc_b = (const float*)d_in[6];

    float* out = (float*)d_out;
    // output layout: y_pred[256] | hidden_seq[B*T*H] | h_t[B*H] | c_t[B*H]
    float* y_pred  = out;
    float* hidden  = out + 256;
    float* h_final = hidden + (size_t)BB * TT * HH;
    float* c_state = h_final + (size_t)BB * HH;

    cudaFuncSetAttribute(lstm_persistent, cudaFuncAttributeMaxDynamicSharedMemorySize,
                         DYN_SMEM);
    cudaFuncSetAttribute(pre_gemm_mma, cudaFuncAttributeMaxDynamicSharedMemorySize,
                         PRE_SMEM);

    wt_split_kernel<<<dim3(ID / 32, GG / 32), 256>>>(W, Wy);
    u_split_kernel<<<dim3(HH / 32, GG / 32), 256>>>(U);
    x_split_kernel<<<(BB * TT * ID) / 4 / 256, 256>>>(X);
    pre_gemm_mma<<<dim3(GG / 128, (BB * TT) / 128), 256, PRE_SMEM>>>(bias);
    bar_init_kernel<<<1, 128>>>();
    lstm_persistent<<<dim3(HH / 32, BB / 64), 256, DYN_SMEM>>>(hidden, c_state,
                                                               h_final);
    fc_kernel<<<BB, 256>>>(h_final, fc_w, fc_b, y_pred);
}

// round 14
// speedup vs baseline: 3.9761x; 1.1232x over previous
#include <cuda_runtime.h>
#include <cuda_fp16.h>
#include <math.h>
#include <stdint.h>

// Problem constants
#define BB   256      // batch
#define TT   256      // time steps
#define ID   256      // input dim
#define HH   1024     // hidden dim
#define GG   4096     // 4*H gates

// Step-kernel tiling: CTA = 128 batch x (4 gates x 16 j), U smem-resident.
#define KC          64
#define NCH         (HH / KC)          // 16 chunks
#define A_STAGE     16384              // h fp16: 128 rows x 128B
#define PRE_BASE    32768
#define PRE_ROW     288                // 256 data + 32 pad
#define U_BASE      (PRE_BASE + 128 * PRE_ROW)       // 69,632
#define U_CHUNK     8192               // 64 rows x 128B per k-chunk
#define DYN_SMEM    (U_BASE + NCH * U_CHUNK)         // 200,704
// Pre-GEMM smem: Ahi 16K + Alo 16K + B 16K
#define PRE_SMEM    49152

typedef unsigned long long ull;

// Scratch (device globals: allocation-free rule)
__device__ float g_pre[(size_t)BB * TT * GG];        // 1 GiB input-gate precompute
__device__ __half g_ut[(size_t)GG * HH];             // U^T fp16 [4096][1024]
__device__ __half g_wt[GG * ID];                     // folded W^T fp16 [4096][256]
__device__ __half g_x_hi[(size_t)BB * TT * ID];      // X fp16 split hi
__device__ __half g_x_lo[(size_t)BB * TT * ID];      // X fp16 split lo
__device__ __half g_h[2][BB * HH];                   // h ping-pong fp16
__device__ __align__(128) unsigned g_bar4[2][32];    // per-mt barriers (padded)

// ---------------------------------------------------------------------------
// helpers
// ---------------------------------------------------------------------------
__device__ __forceinline__ float fast_sigmoid(float x) {
    float e = __expf(-x);
    return __fdividef(1.0f, 1.0f + e);
}
__device__ __forceinline__ float fast_tanh(float x) {
    float e = __expf(2.0f * x);
    return 1.0f - __fdividef(2.0f, e + 1.0f);
}
__device__ __forceinline__ void cp_async16(uint32_t dst, const void* src) {
    asm volatile("cp.async.cg.shared.global [%0], [%1], 16;" :: "r"(dst), "l"(src));
}
__device__ __forceinline__ void ldsm_x4(uint32_t* r, uint32_t addr) {
    asm volatile("ldmatrix.sync.aligned.m8n8.x4.shared.b16 {%0,%1,%2,%3}, [%4];"
                 : "=r"(r[0]), "=r"(r[1]), "=r"(r[2]), "=r"(r[3]) : "r"(addr));
}
// f16 x f16 -> f32 accum
__device__ __forceinline__ void mma_f16_f32(float* d, const uint32_t* a, const uint32_t* b) {
    asm volatile("mma.sync.aligned.m16n8k16.row.col.f32.f16.f16.f32 "
                 "{%0,%1,%2,%3}, {%4,%5,%6,%7}, {%8,%9}, {%0,%1,%2,%3};"
                 : "+f"(d[0]), "+f"(d[1]), "+f"(d[2]), "+f"(d[3])
                 : "r"(a[0]), "r"(a[1]), "r"(a[2]), "r"(a[3]), "r"(b[0]), "r"(b[1]));
}

// ---------------------------------------------------------------------------
// Kernel A: fold Wy into W row 255, transpose -> g_wt[g][k] fp16
// ---------------------------------------------------------------------------
__global__ void wt_split_kernel(const float* __restrict__ W,
                                const float* __restrict__ Wy) {
    __shared__ float tile[32][33];
    const int kb = blockIdx.x * 32;
    const int gb = blockIdx.y * 32;
    const int tx = threadIdx.x & 31;
    const int ty = threadIdx.x >> 5;
#pragma unroll
    for (int i = 0; i < 32; i += 8) {
        int krow = kb + ty + i;
        float v = W[(size_t)krow * GG + gb + tx];
        if (krow == ID - 1) v += Wy[gb + tx];
        tile[ty + i][tx] = v;
    }
    __syncthreads();
#pragma unroll
    for (int i = 0; i < 32; i += 8) {
        int g = gb + ty + i;
        int k = kb + tx;
        g_wt[g * ID + k] = __float2half_rn(tile[tx][ty + i]);
    }
}

// ---------------------------------------------------------------------------
// Kernel B: U^T fp16: g_ut[g][k] = fp16(U[k][g])
// ---------------------------------------------------------------------------
__global__ void u_split_kernel(const float* __restrict__ U) {
    __shared__ float tile[32][33];
    const int kb = blockIdx.x * 32;
    const int gb = blockIdx.y * 32;
    const int tx = threadIdx.x & 31;
    const int ty = threadIdx.x >> 5;
#pragma unroll
    for (int i = 0; i < 32; i += 8)
        tile[ty + i][tx] = U[(size_t)(kb + ty + i) * GG + gb + tx];
    __syncthreads();
#pragma unroll
    for (int i = 0; i < 32; i += 8) {
        int g = gb + ty + i;
        int k = kb + tx;
        g_ut[(size_t)g * HH + k] = __float2half_rn(tile[tx][ty + i]);
    }
}

// ---------------------------------------------------------------------------
// Kernel C: X fp16 split (hi + lo residual)
// ---------------------------------------------------------------------------
__global__ void x_split_kernel(const float* __restrict__ X) {
    size_t i4 = (size_t)blockIdx.x * blockDim.x + threadIdx.x;
    float4 v = *(const float4*)(X + i4 * 4);
    float f[4] = {v.x, v.y, v.z, v.w};
    __half hi[4], lo[4];
#pragma unroll
    for (int e = 0; e < 4; ++e) {
        hi[e] = __float2half_rn(f[e]);
        lo[e] = __float2half_rn(f[e] - __half2float(hi[e]));
    }
    *(__half2*)(g_x_hi + i4 * 4)     = __halves2half2(hi[0], hi[1]);
    *(__half2*)(g_x_hi + i4 * 4 + 2) = __halves2half2(hi[2], hi[3]);
    *(__half2*)(g_x_lo + i4 * 4)     = __halves2half2(lo[0], lo[1]);
    *(__half2*)(g_x_lo + i4 * 4 + 2) = __halves2half2(lo[2], lo[3]);
}

// ---------------------------------------------------------------------------
// Kernel D: tensorized pre-GEMM, fp16 2-pass (unchanged, 689us proven).
// ---------------------------------------------------------------------------
__global__ __launch_bounds__(256, 2) void pre_gemm_mma(
    const float* __restrict__ bias) {
    extern __shared__ char dsm[];
    const uint32_t sA = (uint32_t)__cvta_generic_to_shared(dsm);
    const uint32_t sB = sA + 32768;

    const int tid = threadIdx.x;
    const int wid = tid >> 5;
    const int lane = tid & 31;
    const int mwarp = wid >> 1;
    const int nwarp = wid & 1;
    const int m0 = blockIdx.y * 128;
    const int n0 = blockIdx.x * 128;

    float acc[2][8][4];
#pragma unroll
    for (int mb = 0; mb < 2; ++mb)
#pragma unroll
        for (int nb = 0; nb < 8; ++nb)
#pragma unroll
            for (int r = 0; r < 4; ++r) acc[mb][nb][r] = 0.f;

    for (int kb = 0; kb < ID / 64; ++kb) {
        const int k0 = kb * 64;
        __syncthreads();
#pragma unroll
        for (int i = 0; i < 8; ++i) {
            int idx = i * 256 + tid;
            int mat = idx >> 10;
            int row = (idx >> 3) & 127;
            int gk = idx & 7;
            const __half* src = (mat ? g_x_lo : g_x_hi) +
                (size_t)(m0 + row) * ID + k0 + gk * 8;
            uint32_t dst = sA + mat * 16384 + row * 128 + ((gk ^ (row & 7)) << 4);
            cp_async16(dst, src);
        }
#pragma unroll
        for (int i = 0; i < 4; ++i) {
            int idx = i * 256 + tid;
            int row = idx >> 3;
            int gk = idx & 7;
            const __half* src = g_wt + (size_t)(n0 + row) * ID + k0 + gk * 8;
            uint32_t dst = sB + row * 128 + ((gk ^ (row & 7)) << 4);
            cp_async16(dst, src);
        }
        asm volatile("cp.async.commit_group;" ::: "memory");
        asm volatile("cp.async.wait_group 0;" ::: "memory");
        __syncthreads();

#pragma unroll
        for (int ks = 0; ks < 4; ++ks) {
            uint32_t a_hi[2][4], a_lo[2][4];
#pragma unroll
            for (int mb = 0; mb < 2; ++mb) {
                uint32_t arow = mwarp * 32 + mb * 16 + (lane & 15);
                int gk = ks * 2 + (lane >> 4);
                uint32_t off = arow * 128 + ((gk ^ (arow & 7)) << 4);
                ldsm_x4(a_hi[mb], sA + off);
                ldsm_x4(a_lo[mb], sA + 16384 + off);
            }
#pragma unroll
            for (int nbp = 0; nbp < 4; ++nbp) {
                uint32_t brow = nwarp * 64 + nbp * 16 + (lane & 7) + (lane >> 4) * 8;
                int gk = ks * 2 + ((lane >> 3) & 1);
                uint32_t off = brow * 128 + ((gk ^ (brow & 7)) << 4);
                uint32_t b4[4];
                ldsm_x4(b4, sB + off);
#pragma unroll
                for (int h = 0; h < 2; ++h) {
#pragma unroll
                    for (int mb = 0; mb < 2; ++mb) {
                        mma_f16_f32(acc[mb][nbp * 2 + h], a_hi[mb], b4 + h * 2);
                        mma_f16_f32(acc[mb][nbp * 2 + h], a_lo[mb], b4 + h * 2);
                    }
                }
            }
        }
    }

#pragma unroll
    for (int nb = 0; nb < 8; ++nb) {
        const int col = n0 + nwarp * 64 + nb * 8 + (lane & 3) * 2;
        float2 bv = *(const float2*)(bias + col);
#pragma unroll
        for (int mb = 0; mb < 2; ++mb)
#pragma unroll
            for (int rh = 0; rh < 2; ++rh) {
                int row = m0 + mwarp * 32 + mb * 16 + rh * 8 + (lane >> 2);
                float2 o = make_float2(acc[mb][nb][rh * 2] + bv.x,
                                       acc[mb][nb][rh * 2 + 1] + bv.y);
                *(float2*)(g_pre + (size_t)row * GG + col) = o;
            }
    }
}

// ---------------------------------------------------------------------------
// Kernel E: barrier init (every launch -> graph-replay safe)
// ---------------------------------------------------------------------------
__global__ void bar_init_kernel() {
    if (threadIdx.x < 64)
        ((unsigned*)g_bar4)[threadIdx.x] = 0u;
}

// ---------------------------------------------------------------------------
// Kernel F: persistent LSTM. CTA = 128 batch x (4 gates x 16 j); U slice
// (64 rows x 1024 k fp16 = 128KB) resident in smem for all 256 steps.
// Per step only h (A) + pre stream in. Grid (64, 2) = 128 CTAs, 1/SM.
// ---------------------------------------------------------------------------
__global__ __launch_bounds__(256, 1) void lstm_persistent(
    float* __restrict__ hidden,      // [B][T][H]
    float* __restrict__ c_state,     // [B][H]
    float* __restrict__ h_final) {   // [B][H]
    extern __shared__ char dsm[];
    const int tid = threadIdx.x;
    const int wid = tid >> 5;
    const int lane = tid & 31;
    const int jt = blockIdx.x;       // 0..63 (16 j columns each)
    const int mt = blockIdx.y;       // 0..1 (128 batch rows each)
    const int mwarp = wid >> 1;      // 0..3
    const int jwarp = wid & 1;       // 0..1
    const uint32_t smem0 = (uint32_t)__cvta_generic_to_shared(dsm);

    // ---- one-time: load U slice into resident smem ----
    // rows: gate*16 + j16 (64 rows), chunk c covers k in [c*64, c*64+64)
    {
#pragma unroll
        for (int c = 0; c < NCH; ++c) {
#pragma unroll
            for (int i = 0; i < 2; ++i) {
                int idx = i * 256 + tid;
                int row = idx >> 3;          // 0..63
                int gk = idx & 7;
                int grow = (row >> 4) * HH + jt * 16 + (row & 15);
                const __half* src = g_ut + (size_t)grow * HH + c * KC + gk * 8;
                uint32_t dst = smem0 + U_BASE + c * U_CHUNK + row * 128 +
                               ((gk ^ (row & 7)) << 4);
                cp_async16(dst, src);
            }
        }
    }

    auto issue_pre = [&](int t) {
#pragma unroll
        for (int i = 0; i < 8; ++i) {
            int idx = i * 256 + tid;
            int row = idx >> 4;              // 0..127
            int rest = idx & 15;
            int gate = rest >> 2;
            int g4 = rest & 3;
            const float* src = g_pre + ((size_t)(mt * 128 + row) * TT + t) * GG +
                               gate * HH + jt * 16 + g4 * 4;
            uint32_t dst = smem0 + PRE_BASE + row * PRE_ROW + gate * 64 + g4 * 16;
            cp_async16(dst, src);
        }
    };

    for (int t = 0; t < TT; ++t) {
        float acc[4][2][4];                  // [gate][m-frag][reg]
#pragma unroll
        for (int g = 0; g < 4; ++g)
#pragma unroll
            for (int mb = 0; mb < 2; ++mb)
#pragma unroll
                for (int r = 0; r < 4; ++r) acc[g][mb][r] = 0.f;

        if (t > 0) {
            const __half* hp = g_h[(t - 1) & 1];

            auto issue_A = [&](int c, int s) {
                const int k0 = c * KC;
                const uint32_t sb = smem0 + s * A_STAGE;
#pragma unroll
                for (int i = 0; i < 4; ++i) {
                    int idx = i * 256 + tid;
                    int row = idx >> 3;      // 0..127
                    int gk = idx & 7;
                    const __half* src = hp + (size_t)(mt * 128 + row) * HH + k0 + gk * 8;
                    uint32_t dst = sb + row * 128 + ((gk ^ (row & 7)) << 4);
                    cp_async16(dst, src);
                }
            };

            issue_A(0, 0);
            asm volatile("cp.async.commit_group;" ::: "memory");
            asm volatile("cp.async.wait_group 0;" ::: "memory");
            __syncthreads();

            for (int c = 0; c < NCH; ++c) {
                const int s = c & 1;
                if (c + 1 < NCH) issue_A(c + 1, s ^ 1);
                if (c == 1) issue_pre(t);
                asm volatile("cp.async.commit_group;" ::: "memory");

                const uint32_t sA = smem0 + s * A_STAGE;
                const uint32_t sB = smem0 + U_BASE + c * U_CHUNK;
#pragma unroll
                for (int ks = 0; ks < KC / 16; ++ks) {
                    uint32_t a4[2][4];
#pragma unroll
                    for (int mb = 0; mb < 2; ++mb) {
                        uint32_t arow = mwarp * 32 + mb * 16 + (lane & 15);
                        int gk = ks * 2 + (lane >> 4);
                        uint32_t off = arow * 128 + ((gk ^ (arow & 7)) << 4);
                        ldsm_x4(a4[mb], sA + off);
                    }
#pragma unroll
                    for (int gp = 0; gp < 2; ++gp) {
                        // one ldsm_x4 gathers two gates (lanes 16-31 -> gate 2gp+1)
                        uint32_t brow = (uint32_t)((gp * 2 + (lane >> 4)) * 16 +
                                                   jwarp * 8 + (lane & 7));
                        int gk = ks * 2 + ((lane >> 3) & 1);
                        uint32_t off = brow * 128 + ((gk ^ (brow & 7)) << 4);
                        uint32_t b4[4];
                        ldsm_x4(b4, sB + off);
#pragma unroll
                        for (int mb = 0; mb < 2; ++mb) {
                            mma_f16_f32(acc[gp * 2][mb], a4[mb], b4);
                            mma_f16_f32(acc[gp * 2 + 1][mb], a4[mb], b4 + 2);
                        }
                    }
                }
                if (c + 1 < NCH) {
                    asm volatile("cp.async.wait_group 0;" ::: "memory");
                    __syncthreads();
                }
            }
        } else {
            // t == 0: finish U-resident load + pre tile for t=0.
            issue_pre(0);
            asm volatile("cp.async.commit_group;" ::: "memory");
            asm volatile("cp.async.wait_group 0;" ::: "memory");
            __syncthreads();
        }

        // ---- fused cell-update epilogue (pre read from smem) ----
        // thread owns: 4 batch rows (mb x rh) x 2 j x 4 gates
        const int jcol = jwarp * 8 + (lane & 3) * 2;      // 0..15 within tile
        const int j = jt * 16 + jcol;
#pragma unroll
        for (int mb = 0; mb < 2; ++mb) {
#pragma unroll
            for (int rh = 0; rh < 2; ++rh) {
                const int lrow = mwarp * 32 + mb * 16 + rh * 8 + (lane >> 2);
                const int b = mt * 128 + lrow;
                const char* prs = dsm + PRE_BASE + (size_t)lrow * PRE_ROW;
                float* crow = c_state + (size_t)b * HH;
                float* hrow = hidden + ((size_t)b * TT + t) * HH;
                float2 pi = *(const float2*)(prs + 0 * 64 + jcol * 4);
                float2 pf = *(const float2*)(prs + 1 * 64 + jcol * 4);
                float2 pg = *(const float2*)(prs + 2 * 64 + jcol * 4);
                float2 po = *(const float2*)(prs + 3 * 64 + jcol * 4);
                float2 co = (t > 0) ? *(const float2*)(crow + j)
                                    : make_float2(0.f, 0.f);
                const int r0 = rh * 2;
                float i0 = fast_sigmoid(acc[0][mb][r0]     + pi.x);
                float i1 = fast_sigmoid(acc[0][mb][r0 + 1] + pi.y);
                float f0 = fast_sigmoid(acc[1][mb][r0]     + pf.x);
                float f1 = fast_sigmoid(acc[1][mb][r0 + 1] + pf.y);
                float g0 = fast_tanh(acc[2][mb][r0]     + pg.x);
                float g1 = fast_tanh(acc[2][mb][r0 + 1] + pg.y);
                float o0 = fast_sigmoid(acc[3][mb][r0]     + po.x);
                float o1 = fast_sigmoid(acc[3][mb][r0 + 1] + po.y);
                float cn0 = f0 * co.x + i0 * g0;
                float cn1 = f1 * co.y + i1 * g1;
                float hn0 = o0 * fast_tanh(cn0);
                float hn1 = o1 * fast_tanh(cn1);
                *(float2*)(crow + j) = make_float2(cn0, cn1);
                *(float2*)(hrow + j) = make_float2(hn0, hn1);
                *(__half2*)(g_h[t & 1] + (size_t)b * HH + j) =
                    __halves2half2(__float2half_rn(hn0), __float2half_rn(hn1));
                if (t == TT - 1)
                    *(float2*)(h_final + (size_t)b * HH + j) = make_float2(hn0, hn1);
            }
        }

        // ---- per-mt device barrier (64 CTAs) ----
        if (t < TT - 1) {
            __threadfence();
            __syncthreads();
            if (tid == 0) {
                atomicAdd(&g_bar4[mt][0], 1u);
                const unsigned target = 64u * (unsigned)(t + 1);
                while (atomicAdd(&g_bar4[mt][0], 0u) < target) {}
            }
            __syncthreads();
            __threadfence();
        }
    }
}

// ---------------------------------------------------------------------------
// Kernel G: y_pred[b] = h_final[b,:] . fc_w + fc_b
// ---------------------------------------------------------------------------
__global__ void fc_kernel(const float* __restrict__ h_final,
                          const float* __restrict__ fc_w,
                          const float* __restrict__ fc_b,
                          float* __restrict__ y_pred) {
    int b = blockIdx.x;
    int tid = threadIdx.x;
    float s = 0.f;
    for (int k = tid; k < HH; k += 256)
        s += h_final[b * HH + k] * fc_w[k];
#pragma unroll
    for (int off = 16; off > 0; off >>= 1)
        s += __shfl_down_sync(0xffffffffu, s, off);
    __shared__ float red[8];
    if ((tid & 31) == 0) red[tid >> 5] = s;
    __syncthreads();
    if (tid == 0) {
        float tot = 0.f;
#pragma unroll
        for (int w = 0; w < 8; ++w) tot += red[w];
        y_pred[b] = tot + fc_b[0];
    }
}

// ---------------------------------------------------------------------------
extern "C" void kernel_launch(void* const* d_in, const int* in_sizes, int n_in,
                              void* d_out, int out_size) {
    const float* X    = (const float*)d_in[0];
    const float* W    = (const float*)d_in[1];
    const float* U    = (const float*)d_in[2];
    const float* bias = (const float*)d_in[3];
    const float* Wy   = (const float*)d_in[4];
    const float* fc_w = (const float*)d_in[5];
    const float* fc_b = (const float*)d_in[6];

    float* out = (float*)d_out;
    // output layout: y_pred[256] | hidden_seq[B*T*H] | h_t[B*H] | c_t[B*H]
    float* y_pred  = out;
    float* hidden  = out + 256;
    float* h_final = hidden + (size_t)BB * TT * HH;
    float* c_state = h_final + (size_t)BB * HH;

    cudaFuncSetAttribute(lstm_persistent, cudaFuncAttributeMaxDynamicSharedMemorySize,
                         DYN_SMEM);
    cudaFuncSetAttribute(pre_gemm_mma, cudaFuncAttributeMaxDynamicSharedMemorySize,
                         PRE_SMEM);

    wt_split_kernel<<<dim3(ID / 32, GG / 32), 256>>>(W, Wy);
    u_split_kernel<<<dim3(HH / 32, GG / 32), 256>>>(U);
    x_split_kernel<<<(BB * TT * ID) / 4 / 256, 256>>>(X);
    pre_gemm_mma<<<dim3(GG / 128, (BB * TT) / 128), 256, PRE_SMEM>>>(bias);
    bar_init_kernel<<<1, 64>>>();
    lstm_persistent<<<dim3(HH / 16, BB / 128), 256, DYN_SMEM>>>(hidden, c_state,
                                                                h_final);
    fc_kernel<<<BB, 256>>>(h_final, fc_w, fc_b, y_pred);
}

// round 16
// speedup vs baseline: 4.1799x; 1.0513x over previous
#include <cuda_runtime.h>
#include <cuda_fp16.h>
#include <math.h>
#include <stdint.h>

// Problem constants
#define BB   256      // batch
#define TT   256      // time steps
#define ID   256      // input dim
#define HH   1024     // hidden dim
#define GG   4096     // 4*H gates

// Persistent-kernel tiling: CTA = 128 batch x (4 gates x 16 j).
// U slice (64 rows x 1024 k) + W slice (64 rows x 256 k) resident in smem.
#define KC          64
#define NCH         (HH / KC)          // 16 U chunks
#define NCX         (ID / KC)          // 4 X/W chunks
#define A_BASE      0
#define A_STAGE     16384              // h fp16: 128 rows x 128B
#define X_BASE      32768
#define X_STAGE     16384              // X fp16: 128 rows x 128B
#define U_BASE      65536
#define U_CHUNK     8192               // 64 rows x 128B
#define W_BASE      (U_BASE + NCH * U_CHUNK)      // 196608
#define W_CHUNK     8192
#define DYN_SMEM    (W_BASE + NCX * W_CHUNK)      // 229,376 (224KB)

typedef unsigned long long ull;

// Scratch (device globals: allocation-free rule)
__device__ __half g_ut[(size_t)GG * HH];             // U^T fp16 [4096][1024]
__device__ __half g_wt[GG * ID];                     // folded W^T fp16 [4096][256]
__device__ __half g_x[(size_t)BB * TT * ID];         // X fp16
__device__ __half g_h[2][BB * HH];                   // h ping-pong fp16
__device__ __align__(128) unsigned g_bar4[2][32];    // per-mt barriers (padded)

// ---------------------------------------------------------------------------
// helpers
// ---------------------------------------------------------------------------
__device__ __forceinline__ float fast_sigmoid(float x) {
    float e = __expf(-x);
    return __fdividef(1.0f, 1.0f + e);
}
__device__ __forceinline__ float fast_tanh(float x) {
    float e = __expf(2.0f * x);
    return 1.0f - __fdividef(2.0f, e + 1.0f);
}
__device__ __forceinline__ void cp_async16(uint32_t dst, const void* src) {
    asm volatile("cp.async.cg.shared.global [%0], [%1], 16;" :: "r"(dst), "l"(src));
}
__device__ __forceinline__ void ldsm_x4(uint32_t* r, uint32_t addr) {
    asm volatile("ldmatrix.sync.aligned.m8n8.x4.shared.b16 {%0,%1,%2,%3}, [%4];"
                 : "=r"(r[0]), "=r"(r[1]), "=r"(r[2]), "=r"(r[3]) : "r"(addr));
}
// f16 x f16 -> f32 accum
__device__ __forceinline__ void mma_f16_f32(float* d, const uint32_t* a, const uint32_t* b) {
    asm volatile("mma.sync.aligned.m16n8k16.row.col.f32.f16.f16.f32 "
                 "{%0,%1,%2,%3}, {%4,%5,%6,%7}, {%8,%9}, {%0,%1,%2,%3};"
                 : "+f"(d[0]), "+f"(d[1]), "+f"(d[2]), "+f"(d[3])
                 : "r"(a[0]), "r"(a[1]), "r"(a[2]), "r"(a[3]), "r"(b[0]), "r"(b[1]));
}

// ---------------------------------------------------------------------------
// Kernel A: fold Wy into W row 255, transpose -> g_wt[g][k] fp16
// ---------------------------------------------------------------------------
__global__ void wt_split_kernel(const float* __restrict__ W,
                                const float* __restrict__ Wy) {
    __shared__ float tile[32][33];
    const int kb = blockIdx.x * 32;
    const int gb = blockIdx.y * 32;
    const int tx = threadIdx.x & 31;
    const int ty = threadIdx.x >> 5;
#pragma unroll
    for (int i = 0; i < 32; i += 8) {
        int krow = kb + ty + i;
        float v = W[(size_t)krow * GG + gb + tx];
        if (krow == ID - 1) v += Wy[gb + tx];
        tile[ty + i][tx] = v;
    }
    __syncthreads();
#pragma unroll
    for (int i = 0; i < 32; i += 8) {
        int g = gb + ty + i;
        int k = kb + tx;
        g_wt[g * ID + k] = __float2half_rn(tile[tx][ty + i]);
    }
}

// ---------------------------------------------------------------------------
// Kernel B: U^T fp16: g_ut[g][k] = fp16(U[k][g])
// ---------------------------------------------------------------------------
__global__ void u_split_kernel(const float* __restrict__ U) {
    __shared__ float tile[32][33];
    const int kb = blockIdx.x * 32;
    const int gb = blockIdx.y * 32;
    const int tx = threadIdx.x & 31;
    const int ty = threadIdx.x >> 5;
#pragma unroll
    for (int i = 0; i < 32; i += 8)
        tile[ty + i][tx] = U[(size_t)(kb + ty + i) * GG + gb + tx];
    __syncthreads();
#pragma unroll
    for (int i = 0; i < 32; i += 8) {
        int g = gb + ty + i;
        int k = kb + tx;
        g_ut[(size_t)g * HH + k] = __float2half_rn(tile[tx][ty + i]);
    }
}

// ---------------------------------------------------------------------------
// Kernel C: X fp16 convert
// ---------------------------------------------------------------------------
__global__ void x_split_kernel(const float* __restrict__ X) {
    size_t i4 = (size_t)blockIdx.x * blockDim.x + threadIdx.x;
    float4 v = *(const float4*)(X + i4 * 4);
    *(__half2*)(g_x + i4 * 4)     = __halves2half2(__float2half_rn(v.x),
                                                   __float2half_rn(v.y));
    *(__half2*)(g_x + i4 * 4 + 2) = __halves2half2(__float2half_rn(v.z),
                                                   __float2half_rn(v.w));
}

// ---------------------------------------------------------------------------
// Kernel E: barrier init (every launch -> graph-replay safe)
// ---------------------------------------------------------------------------
__global__ void bar_init_kernel() {
    if (threadIdx.x < 64)
        ((unsigned*)g_bar4)[threadIdx.x] = 0u;
}

// ---------------------------------------------------------------------------
// Kernel F: fully fused persistent LSTM.
// Gates(t) = bias + X[.,t,:]@Wf + h(t-1)@U, all on tensor cores.
// U (128KB) + W (32KB) resident in smem; X-GEMM runs between barrier-arrive
// and barrier-wait so it hides under inter-CTA skew. Grid (64, 2), 1 CTA/SM.
// ---------------------------------------------------------------------------
__global__ __launch_bounds__(256, 1) void lstm_persistent(
    float* __restrict__ hidden,      // [B][T][H]
    float* __restrict__ c_state,     // [B][H]
    float* __restrict__ h_final,     // [B][H]
    const float* __restrict__ bias) {
    extern __shared__ char dsm[];
    const int tid = threadIdx.x;
    const int wid = tid >> 5;
    const int lane = tid & 31;
    const int jt = blockIdx.x;       // 0..63 (16 j columns each)
    const int mt = blockIdx.y;       // 0..1 (128 batch rows each)
    const int mwarp = wid >> 1;      // 0..3
    const int jwarp = wid & 1;       // 0..1
    const uint32_t smem0 = (uint32_t)__cvta_generic_to_shared(dsm);

    // ---- one-time: load U + W slices into resident smem ----
#pragma unroll
    for (int c = 0; c < NCH; ++c) {
#pragma unroll
        for (int i = 0; i < 2; ++i) {
            int idx = i * 256 + tid;
            int row = idx >> 3;          // 0..63
            int gk = idx & 7;
            int grow = (row >> 4) * HH + jt * 16 + (row & 15);
            const __half* src = g_ut + (size_t)grow * HH + c * KC + gk * 8;
            uint32_t dst = smem0 + U_BASE + c * U_CHUNK + row * 128 +
                           ((gk ^ (row & 7)) << 4);
            cp_async16(dst, src);
        }
    }
#pragma unroll
    for (int i = 0; i < 8; ++i) {
        int idx = i * 256 + tid;
        int c = idx >> 9;                // 0..3
        int row = (idx >> 3) & 63;
        int gk = idx & 7;
        int grow = (row >> 4) * HH + jt * 16 + (row & 15);
        const __half* src = g_wt + (size_t)grow * ID + c * KC + gk * 8;
        uint32_t dst = smem0 + W_BASE + c * W_CHUNK + row * 128 +
                       ((gk ^ (row & 7)) << 4);
        cp_async16(dst, src);
    }
    asm volatile("cp.async.commit_group;" ::: "memory");

    // bias for this thread's columns: [gate][e]
    float bv[4][2];
    {
        const int jcol = jt * 16 + jwarp * 8 + (lane & 3) * 2;
#pragma unroll
        for (int g = 0; g < 4; ++g) {
            float2 b2 = *(const float2*)(bias + g * HH + jcol);
            bv[g][0] = b2.x;
            bv[g][1] = b2.y;
        }
    }

    const uint32_t arow_off = mwarp * 32;   // warp m-base within 128-row tile

    for (int t = 0; t < TT; ++t) {
        float acc[4][2][4];                  // [gate][m-frag][reg], init = bias
#pragma unroll
        for (int g = 0; g < 4; ++g)
#pragma unroll
            for (int mb = 0; mb < 2; ++mb)
#pragma unroll
                for (int r = 0; r < 4; ++r) acc[g][mb][r] = bv[g][r & 1];

        // ================= X phase (independent of h; hides under barrier) ==
        auto issue_X = [&](int c, int s) {
            const int k0 = c * KC;
            const uint32_t sb = smem0 + X_BASE + s * X_STAGE;
#pragma unroll
            for (int i = 0; i < 4; ++i) {
                int idx = i * 256 + tid;
                int row = idx >> 3;          // 0..127
                int gk = idx & 7;
                const __half* src = g_x +
                    ((size_t)(mt * 128 + row) * TT + t) * ID + k0 + gk * 8;
                uint32_t dst = sb + row * 128 + ((gk ^ (row & 7)) << 4);
                cp_async16(dst, src);
            }
        };

        issue_X(0, 0);
        asm volatile("cp.async.commit_group;" ::: "memory");
        asm volatile("cp.async.wait_group 0;" ::: "memory");   // also covers U/W at t=0
        __syncthreads();

        for (int c = 0; c < NCX; ++c) {
            const int s = c & 1;
            if (c + 1 < NCX) {
                issue_X(c + 1, s ^ 1);
                asm volatile("cp.async.commit_group;" ::: "memory");
            }
            const uint32_t sA = smem0 + X_BASE + s * X_STAGE;
            const uint32_t sB = smem0 + W_BASE + c * W_CHUNK;
#pragma unroll
            for (int ks = 0; ks < KC / 16; ++ks) {
                uint32_t a4[2][4];
#pragma unroll
                for (int mb = 0; mb < 2; ++mb) {
                    uint32_t arow = arow_off + mb * 16 + (lane & 15);
                    int gk = ks * 2 + (lane >> 4);
                    uint32_t off = arow * 128 + ((gk ^ (arow & 7)) << 4);
                    ldsm_x4(a4[mb], sA + off);
                }
#pragma unroll
                for (int gp = 0; gp < 2; ++gp) {
                    uint32_t brow = (uint32_t)((gp * 2 + (lane >> 4)) * 16 +
                                               jwarp * 8 + (lane & 7));
                    int gk = ks * 2 + ((lane >> 3) & 1);
                    uint32_t off = brow * 128 + ((gk ^ (brow & 7)) << 4);
                    uint32_t b4[4];
                    ldsm_x4(b4, sB + off);
#pragma unroll
                    for (int mb = 0; mb < 2; ++mb) {
                        mma_f16_f32(acc[gp * 2][mb], a4[mb], b4);
                        mma_f16_f32(acc[gp * 2 + 1][mb], a4[mb], b4 + 2);
                    }
                }
            }
            if (c + 1 < NCX) {
                asm volatile("cp.async.wait_group 0;" ::: "memory");
                __syncthreads();
            }
        }

        // ================= h phase (needs barrier from previous step) =======
        if (t > 0) {
            // finish the barrier whose arrive happened at end of step t-1
            if (tid == 0) {
                const unsigned target = 64u * (unsigned)t;
                while (atomicAdd(&g_bar4[mt][0], 0u) < target) {}
            }
            __syncthreads();
            __threadfence();

            const __half* hp = g_h[(t - 1) & 1];
            auto issue_A = [&](int c, int s) {
                const int k0 = c * KC;
                const uint32_t sb = smem0 + A_BASE + s * A_STAGE;
#pragma unroll
                for (int i = 0; i < 4; ++i) {
                    int idx = i * 256 + tid;
                    int row = idx >> 3;      // 0..127
                    int gk = idx & 7;
                    const __half* src = hp + (size_t)(mt * 128 + row) * HH + k0 + gk * 8;
                    uint32_t dst = sb + row * 128 + ((gk ^ (row & 7)) << 4);
                    cp_async16(dst, src);
                }
            };

            issue_A(0, 0);
            asm volatile("cp.async.commit_group;" ::: "memory");
            asm volatile("cp.async.wait_group 0;" ::: "memory");
            __syncthreads();

            for (int c = 0; c < NCH; ++c) {
                const int s = c & 1;
                if (c + 1 < NCH) {
                    issue_A(c + 1, s ^ 1);
                    asm volatile("cp.async.commit_group;" ::: "memory");
                }
                const uint32_t sA = smem0 + A_BASE + s * A_STAGE;
                const uint32_t sB = smem0 + U_BASE + c * U_CHUNK;
#pragma unroll
                for (int ks = 0; ks < KC / 16; ++ks) {
                    uint32_t a4[2][4];
#pragma unroll
                    for (int mb = 0; mb < 2; ++mb) {
                        uint32_t arow = arow_off + mb * 16 + (lane & 15);
                        int gk = ks * 2 + (lane >> 4);
                        uint32_t off = arow * 128 + ((gk ^ (arow & 7)) << 4);
                        ldsm_x4(a4[mb], sA + off);
                    }
#pragma unroll
                    for (int gp = 0; gp < 2; ++gp) {
                        uint32_t brow = (uint32_t)((gp * 2 + (lane >> 4)) * 16 +
                                                   jwarp * 8 + (lane & 7));
                        int gk = ks * 2 + ((lane >> 3) & 1);
                        uint32_t off = brow * 128 + ((gk ^ (brow & 7)) << 4);
                        uint32_t b4[4];
                        ldsm_x4(b4, sB + off);
#pragma unroll
                        for (int mb = 0; mb < 2; ++mb) {
                            mma_f16_f32(acc[gp * 2][mb], a4[mb], b4);
                            mma_f16_f32(acc[gp * 2 + 1][mb], a4[mb], b4 + 2);
                        }
                    }
                }
                if (c + 1 < NCH) {
                    asm volatile("cp.async.wait_group 0;" ::: "memory");
                    __syncthreads();
                }
            }
        }

        // ================= fused cell-update epilogue ======================
        const int jcol = jwarp * 8 + (lane & 3) * 2;
        const int j = jt * 16 + jcol;
#pragma unroll
        for (int mb = 0; mb < 2; ++mb) {
#pragma unroll
            for (int rh = 0; rh < 2; ++rh) {
                const int lrow = mwarp * 32 + mb * 16 + rh * 8 + (lane >> 2);
                const int b = mt * 128 + lrow;
                float* crow = c_state + (size_t)b * HH;
                float* hrow = hidden + ((size_t)b * TT + t) * HH;
                float2 co = (t > 0) ? *(const float2*)(crow + j)
                                    : make_float2(0.f, 0.f);
                const int r0 = rh * 2;
                float i0 = fast_sigmoid(acc[0][mb][r0]);
                float i1 = fast_sigmoid(acc[0][mb][r0 + 1]);
                float f0 = fast_sigmoid(acc[1][mb][r0]);
                float f1 = fast_sigmoid(acc[1][mb][r0 + 1]);
                float g0 = fast_tanh(acc[2][mb][r0]);
                float g1 = fast_tanh(acc[2][mb][r0 + 1]);
                float o0 = fast_sigmoid(acc[3][mb][r0]);
                float o1 = fast_sigmoid(acc[3][mb][r0 + 1]);
                float cn0 = f0 * co.x + i0 * g0;
                float cn1 = f1 * co.y + i1 * g1;
                float hn0 = o0 * fast_tanh(cn0);
                float hn1 = o1 * fast_tanh(cn1);
                *(float2*)(crow + j) = make_float2(cn0, cn1);
                *(float2*)(hrow + j) = make_float2(hn0, hn1);
                *(__half2*)(g_h[t & 1] + (size_t)b * HH + j) =
                    __halves2half2(__float2half_rn(hn0), __float2half_rn(hn1));
                if (t == TT - 1)
                    *(float2*)(h_final + (size_t)b * HH + j) = make_float2(hn0, hn1);
            }
        }

        // ================= barrier ARRIVE only (wait happens after X(t+1)) ==
        if (t < TT - 1) {
            __threadfence();
            __syncthreads();
            if (tid == 0) atomicAdd(&g_bar4[mt][0], 1u);
        }
    }
}

// ---------------------------------------------------------------------------
// Kernel G: y_pred[b] = h_final[b,:] . fc_w + fc_b
// ---------------------------------------------------------------------------
__global__ void fc_kernel(const float* __restrict__ h_final,
                          const float* __restrict__ fc_w,
                          const float* __restrict__ fc_b,
                          float* __restrict__ y_pred) {
    int b = blockIdx.x;
    int tid = threadIdx.x;
    float s = 0.f;
    for (int k = tid; k < HH; k += 256)
        s += h_final[b * HH + k] * fc_w[k];
#pragma unroll
    for (int off = 16; off > 0; off >>= 1)
        s += __shfl_down_sync(0xffffffffu, s, off);
    __shared__ float red[8];
    if ((tid & 31) == 0) red[tid >> 5] = s;
    __syncthreads();
    if (tid == 0) {
        float tot = 0.f;
#pragma unroll
        for (int w = 0; w < 8; ++w) tot += red[w];
        y_pred[b] = tot + fc_b[0];
    }
}

// ---------------------------------------------------------------------------
extern "C" void kernel_launch(void* const* d_in, const int* in_sizes, int n_in,
                              void* d_out, int out_size) {
    const float* X    = (const float*)d_in[0];
    const float* W    = (const float*)d_in[1];
    const float* U    = (const float*)d_in[2];
    const float* bias = (const float*)d_in[3];
    const float* Wy   = (const float*)d_in[4];
    const float* fc_w = (const float*)d_in[5];
    const float* fc_b = (const float*)d_in[6];

    float* out = (float*)d_out;
    // output layout: y_pred[256] | hidden_seq[B*T*H] | h_t[B*H] | c_t[B*H]
    float* y_pred  = out;
    float* hidden  = out + 256;
    float* h_final = hidden + (size_t)BB * TT * HH;
    float* c_state = h_final + (size_t)BB * HH;

    cudaFuncSetAttribute(lstm_persistent, cudaFuncAttributeMaxDynamicSharedMemorySize,
                         DYN_SMEM);

    wt_split_kernel<<<dim3(ID / 32, GG / 32), 256>>>(W, Wy);
    u_split_kernel<<<dim3(HH / 32, GG / 32), 256>>>(U);
    x_split_kernel<<<(BB * TT * ID) / 4 / 256, 256>>>(X);
    bar_init_kernel<<<1, 64>>>();
    lstm_persistent<<<dim3(HH / 16, BB / 128), 256, DYN_SMEM>>>(hidden, c_state,
                                                                h_final, bias);
    fc_kernel<<<BB, 256>>>(h_final, fc_w, fc_b, y_pred);
}

// round 17
// speedup vs baseline: 4.2887x; 1.0260x over previous
#include <cuda_runtime.h>
#include <cuda_fp16.h>
#include <math.h>
#include <stdint.h>

// Problem constants
#define BB   256      // batch
#define TT   256      // time steps
#define ID   256      // input dim
#define HH   1024     // hidden dim
#define GG   4096     // 4*H gates

// Persistent-kernel tiling: CTA = 128 batch x (4 gates x 16 j).
// U slice (64 rows x 1024 k) + W slice (64 rows x 256 k) resident in smem.
// A (h) pipeline: depth-3 prefetch over 4 rotating 16KB stages (0..64KB),
// shared with the X phase's 2 stages (X phase completes before h phase).
#define KC          64
#define NCH         (HH / KC)          // 16 U chunks
#define NCX         (ID / KC)          // 4 X/W chunks
#define STAGE_SZ    16384              // 128 rows x 128B
#define X_BASE      32768              // X uses stages 2,3
#define U_BASE      65536
#define U_CHUNK     8192               // 64 rows x 128B
#define W_BASE      (U_BASE + NCH * U_CHUNK)      // 196608
#define W_CHUNK     8192
#define DYN_SMEM    (W_BASE + NCX * W_CHUNK)      // 229,376 (224KB)

typedef unsigned long long ull;

// Scratch (device globals: allocation-free rule)
__device__ __half g_ut[(size_t)GG * HH];             // U^T fp16 [4096][1024]
__device__ __half g_wt[GG * ID];                     // folded W^T fp16 [4096][256]
__device__ __half g_x[(size_t)BB * TT * ID];         // X fp16
__device__ __half g_h[2][BB * HH];                   // h ping-pong fp16
__device__ __align__(128) unsigned g_bar4[2][32];    // per-mt barriers (padded)

// ---------------------------------------------------------------------------
// helpers
// ---------------------------------------------------------------------------
__device__ __forceinline__ float fast_sigmoid(float x) {
    float e = __expf(-x);
    return __fdividef(1.0f, 1.0f + e);
}
__device__ __forceinline__ float fast_tanh(float x) {
    float e = __expf(2.0f * x);
    return 1.0f - __fdividef(2.0f, e + 1.0f);
}
__device__ __forceinline__ void cp_async16(uint32_t dst, const void* src) {
    asm volatile("cp.async.cg.shared.global [%0], [%1], 16;" :: "r"(dst), "l"(src));
}
__device__ __forceinline__ void ldsm_x4(uint32_t* r, uint32_t addr) {
    asm volatile("ldmatrix.sync.aligned.m8n8.x4.shared.b16 {%0,%1,%2,%3}, [%4];"
                 : "=r"(r[0]), "=r"(r[1]), "=r"(r[2]), "=r"(r[3]) : "r"(addr));
}
// f16 x f16 -> f32 accum
__device__ __forceinline__ void mma_f16_f32(float* d, const uint32_t* a, const uint32_t* b) {
    asm volatile("mma.sync.aligned.m16n8k16.row.col.f32.f16.f16.f32 "
                 "{%0,%1,%2,%3}, {%4,%5,%6,%7}, {%8,%9}, {%0,%1,%2,%3};"
                 : "+f"(d[0]), "+f"(d[1]), "+f"(d[2]), "+f"(d[3])
                 : "r"(a[0]), "r"(a[1]), "r"(a[2]), "r"(a[3]), "r"(b[0]), "r"(b[1]));
}

// ---------------------------------------------------------------------------
// Kernel A: fold Wy into W row 255, transpose -> g_wt[g][k] fp16
// ---------------------------------------------------------------------------
__global__ void wt_split_kernel(const float* __restrict__ W,
                                const float* __restrict__ Wy) {
    __shared__ float tile[32][33];
    const int kb = blockIdx.x * 32;
    const int gb = blockIdx.y * 32;
    const int tx = threadIdx.x & 31;
    const int ty = threadIdx.x >> 5;
#pragma unroll
    for (int i = 0; i < 32; i += 8) {
        int krow = kb + ty + i;
        float v = W[(size_t)krow * GG + gb + tx];
        if (krow == ID - 1) v += Wy[gb + tx];
        tile[ty + i][tx] = v;
    }
    __syncthreads();
#pragma unroll
    for (int i = 0; i < 32; i += 8) {
        int g = gb + ty + i;
        int k = kb + tx;
        g_wt[g * ID + k] = __float2half_rn(tile[tx][ty + i]);
    }
}

// ---------------------------------------------------------------------------
// Kernel B: U^T fp16: g_ut[g][k] = fp16(U[k][g])
// ---------------------------------------------------------------------------
__global__ void u_split_kernel(const float* __restrict__ U) {
    __shared__ float tile[32][33];
    const int kb = blockIdx.x * 32;
    const int gb = blockIdx.y * 32;
    const int tx = threadIdx.x & 31;
    const int ty = threadIdx.x >> 5;
#pragma unroll
    for (int i = 0; i < 32; i += 8)
        tile[ty + i][tx] = U[(size_t)(kb + ty + i) * GG + gb + tx];
    __syncthreads();
#pragma unroll
    for (int i = 0; i < 32; i += 8) {
        int g = gb + ty + i;
        int k = kb + tx;
        g_ut[(size_t)g * HH + k] = __float2half_rn(tile[tx][ty + i]);
    }
}

// ---------------------------------------------------------------------------
// Kernel C: X fp16 convert
// ---------------------------------------------------------------------------
__global__ void x_split_kernel(const float* __restrict__ X) {
    size_t i4 = (size_t)blockIdx.x * blockDim.x + threadIdx.x;
    float4 v = *(const float4*)(X + i4 * 4);
    *(__half2*)(g_x + i4 * 4)     = __halves2half2(__float2half_rn(v.x),
                                                   __float2half_rn(v.y));
    *(__half2*)(g_x + i4 * 4 + 2) = __halves2half2(__float2half_rn(v.z),
                                                   __float2half_rn(v.w));
}

// ---------------------------------------------------------------------------
// Kernel E: barrier init (every launch -> graph-replay safe)
// ---------------------------------------------------------------------------
__global__ void bar_init_kernel() {
    if (threadIdx.x < 64)
        ((unsigned*)g_bar4)[threadIdx.x] = 0u;
}

// ---------------------------------------------------------------------------
// Kernel F: fully fused persistent LSTM.
// ---------------------------------------------------------------------------
__global__ __launch_bounds__(256, 1) void lstm_persistent(
    float* __restrict__ hidden,      // [B][T][H]
    float* __restrict__ c_state,     // [B][H]
    float* __restrict__ h_final,     // [B][H]
    const float* __restrict__ bias) {
    extern __shared__ char dsm[];
    const int tid = threadIdx.x;
    const int wid = tid >> 5;
    const int lane = tid & 31;
    const int jt = blockIdx.x;       // 0..63 (16 j columns each)
    const int mt = blockIdx.y;       // 0..1 (128 batch rows each)
    const int mwarp = wid >> 1;      // 0..3
    const int jwarp = wid & 1;       // 0..1
    const uint32_t smem0 = (uint32_t)__cvta_generic_to_shared(dsm);

    // ---- one-time: load U + W slices into resident smem ----
#pragma unroll
    for (int c = 0; c < NCH; ++c) {
#pragma unroll
        for (int i = 0; i < 2; ++i) {
            int idx = i * 256 + tid;
            int row = idx >> 3;          // 0..63
            int gk = idx & 7;
            int grow = (row >> 4) * HH + jt * 16 + (row & 15);
            const __half* src = g_ut + (size_t)grow * HH + c * KC + gk * 8;
            uint32_t dst = smem0 + U_BASE + c * U_CHUNK + row * 128 +
                           ((gk ^ (row & 7)) << 4);
            cp_async16(dst, src);
        }
    }
#pragma unroll
    for (int i = 0; i < 8; ++i) {
        int idx = i * 256 + tid;
        int c = idx >> 9;                // 0..3
        int row = (idx >> 3) & 63;
        int gk = idx & 7;
        int grow = (row >> 4) * HH + jt * 16 + (row & 15);
        const __half* src = g_wt + (size_t)grow * ID + c * KC + gk * 8;
        uint32_t dst = smem0 + W_BASE + c * W_CHUNK + row * 128 +
                       ((gk ^ (row & 7)) << 4);
        cp_async16(dst, src);
    }
    asm volatile("cp.async.commit_group;" ::: "memory");

    // bias for this thread's columns: [gate][e]
    float bv[4][2];
    {
        const int jcol0 = jt * 16 + jwarp * 8 + (lane & 3) * 2;
#pragma unroll
        for (int g = 0; g < 4; ++g) {
            float2 b2 = *(const float2*)(bias + g * HH + jcol0);
            bv[g][0] = b2.x;
            bv[g][1] = b2.y;
        }
    }

    const uint32_t arow_off = mwarp * 32;
    // c-state lives in registers: [mb][rh][e]
    float creg[2][2][2];
#pragma unroll
    for (int mb = 0; mb < 2; ++mb)
#pragma unroll
        for (int rh = 0; rh < 2; ++rh) { creg[mb][rh][0] = 0.f; creg[mb][rh][1] = 0.f; }

    for (int t = 0; t < TT; ++t) {
        float acc[4][2][4];
#pragma unroll
        for (int g = 0; g < 4; ++g)
#pragma unroll
            for (int mb = 0; mb < 2; ++mb)
#pragma unroll
                for (int r = 0; r < 4; ++r) acc[g][mb][r] = bv[g][r & 1];

        // ================= X phase (independent of h; 2 stages) =============
        auto issue_X = [&](int c, int s) {
            const int k0 = c * KC;
            const uint32_t sb = smem0 + X_BASE + s * STAGE_SZ;
#pragma unroll
            for (int i = 0; i < 4; ++i) {
                int idx = i * 256 + tid;
                int row = idx >> 3;
                int gk = idx & 7;
                const __half* src = g_x +
                    ((size_t)(mt * 128 + row) * TT + t) * ID + k0 + gk * 8;
                uint32_t dst = sb + row * 128 + ((gk ^ (row & 7)) << 4);
                cp_async16(dst, src);
            }
        };

        issue_X(0, 0);
        asm volatile("cp.async.commit_group;" ::: "memory");
        asm volatile("cp.async.wait_group 0;" ::: "memory");   // covers U/W at t=0
        __syncthreads();

        for (int c = 0; c < NCX; ++c) {
            const int s = c & 1;
            if (c + 1 < NCX) {
                issue_X(c + 1, s ^ 1);
                asm volatile("cp.async.commit_group;" ::: "memory");
            }
            const uint32_t sA = smem0 + X_BASE + s * STAGE_SZ;
            const uint32_t sB = smem0 + W_BASE + c * W_CHUNK;
#pragma unroll
            for (int ks = 0; ks < KC / 16; ++ks) {
                uint32_t a4[2][4];
#pragma unroll
                for (int mb = 0; mb < 2; ++mb) {
                    uint32_t arow = arow_off + mb * 16 + (lane & 15);
                    int gk = ks * 2 + (lane >> 4);
                    uint32_t off = arow * 128 + ((gk ^ (arow & 7)) << 4);
                    ldsm_x4(a4[mb], sA + off);
                }
#pragma unroll
                for (int gp = 0; gp < 2; ++gp) {
                    uint32_t brow = (uint32_t)((gp * 2 + (lane >> 4)) * 16 +
                                               jwarp * 8 + (lane & 7));
                    int gk = ks * 2 + ((lane >> 3) & 1);
                    uint32_t off = brow * 128 + ((gk ^ (brow & 7)) << 4);
                    uint32_t b4[4];
                    ldsm_x4(b4, sB + off);
#pragma unroll
                    for (int mb = 0; mb < 2; ++mb) {
                        mma_f16_f32(acc[gp * 2][mb], a4[mb], b4);
                        mma_f16_f32(acc[gp * 2 + 1][mb], a4[mb], b4 + 2);
                    }
                }
            }
            if (c + 1 < NCX) {
                asm volatile("cp.async.wait_group 0;" ::: "memory");
                __syncthreads();
            }
        }

        // ================= h phase (after barrier; depth-3 A pipeline) ======
        if (t > 0) {
            if (tid == 0) {
                const unsigned target = 64u * (unsigned)t;
                unsigned v;
                do {
                    asm volatile("ld.acquire.gpu.u32 %0, [%1];"
                                 : "=r"(v) : "l"(&g_bar4[mt][0]) : "memory");
                    if (v >= target) break;
                    __nanosleep(32);
                } while (true);
            }
            __syncthreads();
            __threadfence();

            const __half* hp = g_h[(t - 1) & 1];
            auto issue_A = [&](int c) {
                const int k0 = c * KC;
                const uint32_t sb = smem0 + (c & 3) * STAGE_SZ;
#pragma unroll
                for (int i = 0; i < 4; ++i) {
                    int idx = i * 256 + tid;
                    int row = idx >> 3;
                    int gk = idx & 7;
                    const __half* src = hp + (size_t)(mt * 128 + row) * HH + k0 + gk * 8;
                    uint32_t dst = sb + row * 128 + ((gk ^ (row & 7)) << 4);
                    cp_async16(dst, src);
                }
            };

            // prime: chunks 0,1,2 in flight (3 groups)
            issue_A(0);
            asm volatile("cp.async.commit_group;" ::: "memory");
            issue_A(1);
            asm volatile("cp.async.commit_group;" ::: "memory");
            issue_A(2);
            asm volatile("cp.async.commit_group;" ::: "memory");
            asm volatile("cp.async.wait_group 2;" ::: "memory");   // chunk 0 ready
            __syncthreads();

            for (int c = 0; c < NCH; ++c) {
                const uint32_t sA = smem0 + (c & 3) * STAGE_SZ;
                const uint32_t sB = smem0 + U_BASE + c * U_CHUNK;
#pragma unroll
                for (int ks = 0; ks < KC / 16; ++ks) {
                    uint32_t a4[2][4];
#pragma unroll
                    for (int mb = 0; mb < 2; ++mb) {
                        uint32_t arow = arow_off + mb * 16 + (lane & 15);
                        int gk = ks * 2 + (lane >> 4);
                        uint32_t off = arow * 128 + ((gk ^ (arow & 7)) << 4);
                        ldsm_x4(a4[mb], sA + off);
                    }
#pragma unroll
                    for (int gp = 0; gp < 2; ++gp) {
                        uint32_t brow = (uint32_t)((gp * 2 + (lane >> 4)) * 16 +
                                                   jwarp * 8 + (lane & 7));
                        int gk = ks * 2 + ((lane >> 3) & 1);
                        uint32_t off = brow * 128 + ((gk ^ (brow & 7)) << 4);
                        uint32_t b4[4];
                        ldsm_x4(b4, sB + off);
#pragma unroll
                        for (int mb = 0; mb < 2; ++mb) {
                            mma_f16_f32(acc[gp * 2][mb], a4[mb], b4);
                            mma_f16_f32(acc[gp * 2 + 1][mb], a4[mb], b4 + 2);
                        }
                    }
                }
                if (c + 1 < NCH) {
                    __syncthreads();            // all warps done reading stage (c&3)
                    if (c + 3 < NCH) issue_A(c + 3);
                    asm volatile("cp.async.commit_group;" ::: "memory");   // may be empty
                    asm volatile("cp.async.wait_group 2;" ::: "memory");   // chunk c+1 done
                    __syncthreads();
                }
            }
        }

        // ================= epilogue: cell update ===========================
        const int jcol = jwarp * 8 + (lane & 3) * 2;
        const int j = jt * 16 + jcol;
        float hreg[2][2][2];
#pragma unroll
        for (int mb = 0; mb < 2; ++mb) {
#pragma unroll
            for (int rh = 0; rh < 2; ++rh) {
                const int lrow = mwarp * 32 + mb * 16 + rh * 8 + (lane >> 2);
                const int b = mt * 128 + lrow;
                const int r0 = rh * 2;
                float i0 = fast_sigmoid(acc[0][mb][r0]);
                float i1 = fast_sigmoid(acc[0][mb][r0 + 1]);
                float f0 = fast_sigmoid(acc[1][mb][r0]);
                float f1 = fast_sigmoid(acc[1][mb][r0 + 1]);
                float g0 = fast_tanh(acc[2][mb][r0]);
                float g1 = fast_tanh(acc[2][mb][r0 + 1]);
                float o0 = fast_sigmoid(acc[3][mb][r0]);
                float o1 = fast_sigmoid(acc[3][mb][r0 + 1]);
                float cn0 = f0 * creg[mb][rh][0] + i0 * g0;
                float cn1 = f1 * creg[mb][rh][1] + i1 * g1;
                float hn0 = o0 * fast_tanh(cn0);
                float hn1 = o1 * fast_tanh(cn1);
                creg[mb][rh][0] = cn0;
                creg[mb][rh][1] = cn1;
                hreg[mb][rh][0] = hn0;
                hreg[mb][rh][1] = hn1;
                // fp16 h for the next step's GEMM (the only cross-CTA data)
                *(__half2*)(g_h[t & 1] + (size_t)b * HH + j) =
                    __halves2half2(__float2half_rn(hn0), __float2half_rn(hn1));
            }
        }

        // ---- publish early: only g_h needs to be visible ----
        if (t < TT - 1) {
            __threadfence();
            __syncthreads();
            if (tid == 0) atomicAdd(&g_bar4[mt][0], 1u);
        }

        // ---- off-critical-path fp32 outputs ----
#pragma unroll
        for (int mb = 0; mb < 2; ++mb) {
#pragma unroll
            for (int rh = 0; rh < 2; ++rh) {
                const int lrow = mwarp * 32 + mb * 16 + rh * 8 + (lane >> 2);
                const int b = mt * 128 + lrow;
                *(float2*)(hidden + ((size_t)b * TT + t) * HH + j) =
                    make_float2(hreg[mb][rh][0], hreg[mb][rh][1]);
                if (t == TT - 1) {
                    *(float2*)(h_final + (size_t)b * HH + j) =
                        make_float2(hreg[mb][rh][0], hreg[mb][rh][1]);
                    *(float2*)(c_state + (size_t)b * HH + j) =
                        make_float2(creg[mb][rh][0], creg[mb][rh][1]);
                }
            }
        }
    }
}

// ---------------------------------------------------------------------------
// Kernel G: y_pred[b] = h_final[b,:] . fc_w + fc_b
// ---------------------------------------------------------------------------
__global__ void fc_kernel(const float* __restrict__ h_final,
                          const float* __restrict__ fc_w,
                          const float* __restrict__ fc_b,
                          float* __restrict__ y_pred) {
    int b = blockIdx.x;
    int tid = threadIdx.x;
    float s = 0.f;
    for (int k = tid; k < HH; k += 256)
        s += h_final[b * HH + k] * fc_w[k];
#pragma unroll
    for (int off = 16; off > 0; off >>= 1)
        s += __shfl_down_sync(0xffffffffu, s, off);
    __shared__ float red[8];
    if ((tid & 31) == 0) red[tid >> 5] = s;
    __syncthreads();
    if (tid == 0) {
        float tot = 0.f;
#pragma unroll
        for (int w = 0; w < 8; ++w) tot += red[w];
        y_pred[b] = tot + fc_b[0];
    }
}

// ---------------------------------------------------------------------------
extern "C" void kernel_launch(void* const* d_in, const int* in_sizes, int n_in,
                              void* d_out, int out_size) {
    const float* X    = (const float*)d_in[0];
    const float* W    = (const float*)d_in[1];
    const float* U    = (const float*)d_in[2];
    const float* bias = (const float*)d_in[3];
    const float* Wy   = (const float*)d_in[4];
    const float* fc_w = (const float*)d_in[5];
    const float* fc_b = (const float*)d_in[6];

    float* out = (float*)d_out;
    // output layout: y_pred[256] | hidden_seq[B*T*H] | h_t[B*H] | c_t[B*H]
    float* y_pred  = out;
    float* hidden  = out + 256;
    float* h_final = hidden + (size_t)BB * TT * HH;
    float* c_state = h_final + (size_t)BB * HH;

    cudaFuncSetAttribute(lstm_persistent, cudaFuncAttributeMaxDynamicSharedMemorySize,
                         DYN_SMEM);

    wt_split_kernel<<<dim3(ID / 32, GG / 32), 256>>>(W, Wy);
    u_split_kernel<<<dim3(HH / 32, GG / 32), 256>>>(U);
    x_split_kernel<<<(BB * TT * ID) / 4 / 256, 256>>>(X);
    bar_init_kernel<<<1, 64>>>();
    lstm_persistent<<<dim3(HH / 16, BB / 128), 256, DYN_SMEM>>>(hidden, c_state,
                                                                h_final, bias);
    fc_kernel<<<BB, 256>>>(h_final, fc_w, fc_b, y_pred);
}